// round 8
// baseline (speedup 1.0000x reference)
#include <cuda_runtime.h>
#include <cuda_fp16.h>
#include <math.h>
#include <stdint.h>

// Problem constants
#define BB    2
#define TT    2048
#define CCd   1024
#define NHh   16
#define NKVh  4
#define HDd   64
#define MMem  64
#define SSs   (MMem + TT)   // 2112

// Scratch (device globals; allocation-free per harness rules)
__device__ float  g_qt[BB*TT*NHh*HDd];    // QKV gemm outs: [B*T][1024]
__device__ float  g_kt[BB*TT*NKVh*HDd];   // [B*T][256]
__device__ float  g_vt[BB*TT*NKVh*HDd];   // [B*T][256]
__device__ __half g_qh[BB*NHh*TT*HDd];    // [b][h][t][d]   fp16
__device__ __half g_kh[BB*NKVh*SSs*HDd];  // [b][kv][s][d]  fp16
__device__ __half g_vh[BB*NKVh*SSs*HDd];  // [b][kv][s][d]  fp16
__device__ float  g_y [BB*TT*NHh*HDd];    // attn out [B*T][1024]

// ---------------------------------------------------------------------------
// fp16 helpers
// ---------------------------------------------------------------------------
__device__ __forceinline__ uint32_t h2u(__half2 h) { return *(uint32_t*)&h; }
__device__ __forceinline__ uint32_t packh(float a, float b) {
    __half2 t = __floats2half2_rn(a, b);
    return h2u(t);
}

__device__ __forceinline__ void mma_f16(float* c, const uint32_t* a, const uint32_t* b) {
    asm("mma.sync.aligned.m16n8k16.row.col.f32.f16.f16.f32 "
        "{%0,%1,%2,%3},{%4,%5,%6,%7},{%8,%9},{%0,%1,%2,%3};"
        : "+f"(c[0]), "+f"(c[1]), "+f"(c[2]), "+f"(c[3])
        : "r"(a[0]), "r"(a[1]), "r"(a[2]), "r"(a[3]), "r"(b[0]), "r"(b[1]));
}

#define LDSM_X4(r0,r1,r2,r3,addr) \
    asm volatile("ldmatrix.sync.aligned.m8n8.x4.shared.b16 {%0,%1,%2,%3}, [%4];" \
                 : "=r"(r0), "=r"(r1), "=r"(r2), "=r"(r3) : "r"(addr))
#define LDSM_X4_T(r0,r1,r2,r3,addr) \
    asm volatile("ldmatrix.sync.aligned.m8n8.x4.trans.shared.b16 {%0,%1,%2,%3}, [%4];" \
                 : "=r"(r0), "=r"(r1), "=r"(r2), "=r"(r3) : "r"(addr))

__device__ __forceinline__ uint32_t smem_u32(const void* p) {
    uint32_t a;
    asm("{ .reg .u64 t; cvta.to.shared.u64 t, %1; cvt.u32.u64 %0, t; }" : "=r"(a) : "l"(p));
    return a;
}

#define CPA16(dst, src) \
    asm volatile("cp.async.ca.shared.global [%0], [%1], 16;" :: "r"(dst), "l"(src) : "memory")

// ---------------------------------------------------------------------------
// fp16 NT GEMM with A-side hi/lo split (unchanged from R7).
// ---------------------------------------------------------------------------
#define GLD 20
__global__ __launch_bounds__(256) void gemm_f16_nt(
    const float* __restrict__ A, const float* __restrict__ Bw,
    float* __restrict__ Cm, int N, int K)
{
    __shared__ uint32_t Ah[128*GLD];
    __shared__ uint32_t Al[128*GLD];
    __shared__ uint32_t Bs[128*GLD];
    const int tid = threadIdx.x;
    const int lane = tid & 31, wid = tid >> 5;
    const int wm = wid & 3, wn = wid >> 2;
    const int g = lane >> 2, tg = lane & 3;
    const int m0 = blockIdx.y * 128;
    const int n0 = blockIdx.x * 128;

    float acc[2][8][4] = {};

    for (int k0 = 0; k0 < K; k0 += 32) {
#pragma unroll
        for (int q = 0; q < 4; q++) {
            int idx = q * 256 + tid;
            int row = idx >> 3, kq = (idx & 7) * 4;
            float4 av = *(const float4*)(A + (size_t)(m0 + row) * K + k0 + kq);
            __half2 h0 = __floats2half2_rn(av.x, av.y);
            __half2 h1 = __floats2half2_rn(av.z, av.w);
            float2 f0 = __half22float2(h0), f1 = __half22float2(h1);
            *(uint2*)&Ah[row*GLD + (kq >> 1)] = make_uint2(h2u(h0), h2u(h1));
            *(uint2*)&Al[row*GLD + (kq >> 1)] = make_uint2(
                packh(av.x - f0.x, av.y - f0.y), packh(av.z - f1.x, av.w - f1.y));
            float4 bv = *(const float4*)(Bw + (size_t)(n0 + row) * K + k0 + kq);
            *(uint2*)&Bs[row*GLD + (kq >> 1)] = make_uint2(
                packh(bv.x, bv.y), packh(bv.z, bv.w));
        }
        __syncthreads();
#pragma unroll
        for (int ks = 0; ks < 2; ks++) {
            const int kp = ks * 8;
            uint32_t ah[2][4], al[2][4], b[8][2];
#pragma unroll
            for (int am = 0; am < 2; am++) {
                int r = wm*32 + am*16 + g;
                ah[am][0] = Ah[r*GLD + kp + tg];
                ah[am][1] = Ah[(r+8)*GLD + kp + tg];
                ah[am][2] = Ah[r*GLD + kp + tg + 4];
                ah[am][3] = Ah[(r+8)*GLD + kp + tg + 4];
                al[am][0] = Al[r*GLD + kp + tg];
                al[am][1] = Al[(r+8)*GLD + kp + tg];
                al[am][2] = Al[r*GLD + kp + tg + 4];
                al[am][3] = Al[(r+8)*GLD + kp + tg + 4];
            }
#pragma unroll
            for (int an = 0; an < 8; an++) {
                int c = wn*64 + an*8 + g;
                b[an][0] = Bs[c*GLD + kp + tg];
                b[an][1] = Bs[c*GLD + kp + tg + 4];
            }
#pragma unroll
            for (int am = 0; am < 2; am++)
#pragma unroll
                for (int an = 0; an < 8; an++) {
                    mma_f16(acc[am][an], ah[am], b[an]);
                    mma_f16(acc[am][an], al[am], b[an]);
                }
        }
        __syncthreads();
    }

#pragma unroll
    for (int am = 0; am < 2; am++)
#pragma unroll
        for (int an = 0; an < 8; an++) {
            int r = m0 + wm*32 + am*16 + g;
            int cc = n0 + wn*64 + an*8 + tg*2;
            *(float2*)(Cm + (size_t)r*N + cc)     = make_float2(acc[am][an][0], acc[am][an][1]);
            *(float2*)(Cm + (size_t)(r+8)*N + cc) = make_float2(acc[am][an][2], acc[am][an][3]);
        }
}

// ---------------------------------------------------------------------------
// Postprocess: now writes Q/K/V as fp16 (one rounding, identical values to
// the per-tile rounding the R7 attention kernel performed).
// ---------------------------------------------------------------------------
__device__ __forceinline__ float warpsum32(float v) {
#pragma unroll
    for (int o = 16; o > 0; o >>= 1) v += __shfl_xor_sync(0xffffffffu, v, o);
    return v;
}

__global__ void postproc(const float* __restrict__ x,   const float* __restrict__ ve,
                         const float* __restrict__ cosT,const float* __restrict__ sinT,
                         const float* __restrict__ Wg,  const float* __restrict__ memk,
                         const float* __restrict__ memv,const float* __restrict__ vscale)
{
    const int gg   = blockIdx.x * blockDim.x + threadIdx.x;
    const int w    = gg >> 5;
    const int lane = gg & 31;
    const int NQ = BB*TT*NHh;
    const int NK = BB*TT*NKVh;
    const int NV = NK;

    if (w < NQ) {
        int h = w % NHh; int t = (w / NHh) % TT; int b = w / (NHh * TT);
        const float* src = g_qt + (size_t)(b*TT + t) * CCd + h * HDd;
        float x1 = src[lane], x2 = src[lane + 32];
        float c = cosT[t*32 + lane], s = sinT[t*32 + lane];
        float o1 = x1*c - x2*s, o2 = x1*s + x2*c;
        float ss = warpsum32(o1*o1 + o2*o2);
        float r = rsqrtf(ss * (1.0f/HDd) + 1e-6f) * 1.2f;
        __half* dst = g_qh + (size_t)((b*NHh + h)*TT + t) * HDd;
        dst[lane] = __float2half(o1*r); dst[lane + 32] = __float2half(o2*r);
    } else if (w < NQ + NK) {
        int w2 = w - NQ;
        int n = w2 % NKVh; int t = (w2 / NKVh) % TT; int b = w2 / (NKVh * TT);
        const float* src = g_kt + (size_t)(b*TT + t) * (NKVh*HDd) + n * HDd;
        float x1 = src[lane], x2 = src[lane + 32];
        float c = cosT[t*32 + lane], s = sinT[t*32 + lane];
        float o1 = x1*c - x2*s, o2 = x1*s + x2*c;
        float ss = warpsum32(o1*o1 + o2*o2);
        float r = rsqrtf(ss * (1.0f/HDd) + 1e-6f) * 1.2f;
        __half* dst = g_kh + (size_t)((b*NKVh + n)*SSs + (MMem + t)) * HDd;
        dst[lane] = __float2half(o1*r); dst[lane + 32] = __float2half(o2*r);
    } else if (w < NQ + NK + NV) {
        int w3 = w - NQ - NK;
        int n = w3 % NKVh; int t = (w3 / NKVh) % TT; int b = w3 / (NKVh * TT);
        float gp = x[(size_t)(b*TT + t)*CCd + lane] * Wg[n*32 + lane];
        float dot = warpsum32(gp);
        float gate = 3.0f / (1.0f + __expf(-dot));
        const float* src = g_vt + (size_t)(b*TT + t) * (NKVh*HDd) + n * HDd;
        const float* vep = ve  + (size_t)(b*TT + t) * (NKVh*HDd) + n * HDd;
        float o1 = src[lane]      + gate * vep[lane];
        float o2 = src[lane + 32] + gate * vep[lane + 32];
        __half* dst = g_vh + (size_t)((b*NKVh + n)*SSs + (MMem + t)) * HDd;
        dst[lane] = __float2half(o1); dst[lane + 32] = __float2half(o2);
    } else {
        int w4 = w - NQ - NK - NV;
        int n = w4 % NKVh; int j = (w4 / NKVh) % MMem; int b = w4 / (NKVh * MMem);
        const float* mkp = memk + (size_t)(j*NKVh + n) * HDd;
        float x1 = mkp[lane], x2 = mkp[lane + 32];
        float ss = warpsum32(x1*x1 + x2*x2);
        float r = rsqrtf(ss * (1.0f/HDd) + 1e-6f) * 1.2f;
        __half* kd = g_kh + (size_t)((b*NKVh + n)*SSs + j) * HDd;
        kd[lane] = __float2half(x1*r); kd[lane + 32] = __float2half(x2*r);
        const float* mvp = memv + (size_t)(j*NKVh + n) * HDd;
        float vs = vscale[0];
        __half* vd = g_vh + (size_t)((b*NKVh + n)*SSs + j) * HDd;
        vd[lane] = __float2half(mvp[lane] * vs); vd[lane + 32] = __float2half(mvp[lane + 32] * vs);
    }
}

// ---------------------------------------------------------------------------
// fp16 flash attention with cp.async double-buffered K/V tiles.
// Block = 128 q-rows x 64-key tiles; 8 warps, each owns 16 q-rows x 64 keys.
// K/V live in gmem as fp16 -> cp.async 16B chunks straight into smem
// (pitch 144 B = conflict-free LDSM, same addressing as R7).
// Dyn smem: 2 stages x (K 9216 + V 9216) + Ps 18432 = 55296 B.
// ---------------------------------------------------------------------------
#define KLD 36   // u32 per row: 32 data + 4 pad = 144 B
#define STAGE_U32 (2*64*KLD)          // K+V per stage (4608 u32)
#define PS_OFF    (2*STAGE_U32)       // 9216 u32
#define ATTN_SMEM ((PS_OFF + 128*KLD) * 4)   // 55296 B

__global__ __launch_bounds__(256) void attn_f16()
{
    extern __shared__ uint32_t sm[];
    uint32_t* Ps = sm + PS_OFF;

    const int tid = threadIdx.x;
    const int lane = tid & 31, wid = tid >> 5;
    const int g = lane >> 2, tg = lane & 3;
    const int qi = (int)(gridDim.x - 1 - blockIdx.x);   // long blocks first
    const int h = blockIdx.y, b = blockIdx.z;
    const int t0 = qi * 128;
    const int kvh = h >> 2;

    const __half* qptr = g_qh + (size_t)(b*NHh  + h  ) * TT  * HDd;
    const __half* kptr = g_kh + (size_t)(b*NKVh + kvh) * SSs * HDd;
    const __half* vptr = g_vh + (size_t)(b*NKVh + kvh) * SSs * HDd;

    const uint32_t sm_b = smem_u32(sm);

    // cp.async fill: 2 chunks/thread per matrix (64 rows x 8 x16B chunks)
    const int f_row = tid >> 3, f_c8 = tid & 7;

    // ldmatrix lane->address components (identical to R7)
    const int koK = (lane & 7) + ((lane & 16) >> 1);
    const int doK = lane & 8;
    const int koV = lane & 15;
    const int doV = (lane & 16) >> 1;

    // Q fragments (fp16 in gmem -> direct u32 loads)
    const int rq1 = t0 + wid*16 + g;
    uint32_t qa[4][4];
#pragma unroll
    for (int s8 = 0; s8 < 4; s8++) {
        int d0 = s8*16 + 2*tg;
        qa[s8][0] = *(const uint32_t*)(qptr + (size_t)rq1*HDd + d0);
        qa[s8][1] = *(const uint32_t*)(qptr + (size_t)(rq1+8)*HDd + d0);
        qa[s8][2] = *(const uint32_t*)(qptr + (size_t)rq1*HDd + d0 + 8);
        qa[s8][3] = *(const uint32_t*)(qptr + (size_t)(rq1+8)*HDd + d0 + 8);
    }

    float o[8][4] = {};
    float m1 = -INFINITY, m2 = -INFINITY, l1 = 0.0f, l2 = 0.0f;

    const int nkt = 2*qi + 3;

    // prologue: issue tile 0 into stage 0
    {
        uint32_t kb = sm_b + f_row*144 + f_c8*16;
        CPA16(kb,                 kptr + (size_t)f_row*HDd + f_c8*8);
        CPA16(kb + 64*KLD*4,      vptr + (size_t)f_row*HDd + f_c8*8);
        uint32_t kb2 = kb + 32*144;
        CPA16(kb2,                kptr + (size_t)(f_row+32)*HDd + f_c8*8);
        CPA16(kb2 + 64*KLD*4,     vptr + (size_t)(f_row+32)*HDd + f_c8*8);
        asm volatile("cp.async.commit_group;" ::: "memory");
    }

    for (int kt = 0; kt < nkt; kt++) {
        // prefetch next tile into the other stage, then wait for current
        if (kt + 1 < nkt) {
            uint32_t sb = sm_b + ((kt+1) & 1) * STAGE_U32 * 4;
            const __half* kq = kptr + (size_t)((kt+1)*64 + f_row)*HDd + f_c8*8;
            const __half* vq = vptr + (size_t)((kt+1)*64 + f_row)*HDd + f_c8*8;
            uint32_t kb = sb + f_row*144 + f_c8*16;
            CPA16(kb,             kq);
            CPA16(kb + 64*KLD*4,  vq);
            CPA16(kb + 32*144,            kq + 32*HDd);
            CPA16(kb + 32*144 + 64*KLD*4, vq + 32*HDd);
            asm volatile("cp.async.commit_group;" ::: "memory");
            asm volatile("cp.async.wait_group 1;" ::: "memory");
        } else {
            asm volatile("cp.async.wait_group 0;" ::: "memory");
        }
        __syncthreads();

        const uint32_t ks_b = sm_b + (kt & 1) * STAGE_U32 * 4;
        const uint32_t vs_b = ks_b + 64*KLD*4;

        // S = Q K^T
        float s[8][4] = {};
#pragma unroll
        for (int s8 = 0; s8 < 4; s8++) {
#pragma unroll
            for (int anp = 0; anp < 4; anp++) {
                uint32_t r0, r1, r2, r3;
                uint32_t addr = ks_b + (((anp*16 + koK)*72) + s8*16 + doK) * 2;
                LDSM_X4(r0, r1, r2, r3, addr);
                uint32_t b0[2] = {r0, r1}, b1[2] = {r2, r3};
                mma_f16(s[2*anp],   qa[s8], b0);
                mma_f16(s[2*anp+1], qa[s8], b1);
            }
        }

        // scale + causal mask
        const bool dg = (kt >= 2*qi + 1);
#pragma unroll
        for (int an = 0; an < 8; an++) {
            int j0 = kt*64 + an*8 + tg*2 - MMem;
            s[an][0] *= 0.125f; s[an][1] *= 0.125f;
            s[an][2] *= 0.125f; s[an][3] *= 0.125f;
            if (dg) {
                if (j0     > rq1)   s[an][0] = -INFINITY;
                if (j0 + 1 > rq1)   s[an][1] = -INFINITY;
                if (j0     > rq1+8) s[an][2] = -INFINITY;
                if (j0 + 1 > rq1+8) s[an][3] = -INFINITY;
            }
        }

        // online softmax
        float tm1 = -INFINITY, tm2 = -INFINITY;
#pragma unroll
        for (int an = 0; an < 8; an++) {
            tm1 = fmaxf(tm1, fmaxf(s[an][0], s[an][1]));
            tm2 = fmaxf(tm2, fmaxf(s[an][2], s[an][3]));
        }
        tm1 = fmaxf(tm1, __shfl_xor_sync(0xffffffffu, tm1, 1));
        tm1 = fmaxf(tm1, __shfl_xor_sync(0xffffffffu, tm1, 2));
        tm2 = fmaxf(tm2, __shfl_xor_sync(0xffffffffu, tm2, 1));
        tm2 = fmaxf(tm2, __shfl_xor_sync(0xffffffffu, tm2, 2));

        float mn1 = fmaxf(m1, tm1), mn2 = fmaxf(m2, tm2);
        float sc1 = __expf(m1 - mn1), sc2 = __expf(m2 - mn2);
        m1 = mn1; m2 = mn2;
        l1 *= sc1; l2 *= sc2;
#pragma unroll
        for (int dn = 0; dn < 8; dn++) {
            o[dn][0] *= sc1; o[dn][1] *= sc1;
            o[dn][2] *= sc2; o[dn][3] *= sc2;
        }
        float rs1 = 0.0f, rs2 = 0.0f;
#pragma unroll
        for (int an = 0; an < 8; an++) {
            s[an][0] = __expf(s[an][0] - mn1); s[an][1] = __expf(s[an][1] - mn1);
            s[an][2] = __expf(s[an][2] - mn2); s[an][3] = __expf(s[an][3] - mn2);
            rs1 += s[an][0] + s[an][1];
            rs2 += s[an][2] + s[an][3];
        }
        rs1 += __shfl_xor_sync(0xffffffffu, rs1, 1);
        rs1 += __shfl_xor_sync(0xffffffffu, rs1, 2);
        rs2 += __shfl_xor_sync(0xffffffffu, rs2, 1);
        rs2 += __shfl_xor_sync(0xffffffffu, rs2, 2);
        l1 += rs1; l2 += rs2;

        // P -> warp-private smem rows (packed fp16x2 along keys)
        const int pr = wid*16 + g;
#pragma unroll
        for (int an = 0; an < 8; an++) {
            Ps[pr*KLD + an*4 + tg]     = packh(s[an][0], s[an][1]);
            Ps[(pr+8)*KLD + an*4 + tg] = packh(s[an][2], s[an][3]);
        }
        __syncwarp();

        // O += P V
#pragma unroll
        for (int k8 = 0; k8 < 4; k8++) {
            uint32_t a[4];
            a[0] = Ps[pr*KLD + k8*8 + tg];
            a[1] = Ps[(pr+8)*KLD + k8*8 + tg];
            a[2] = Ps[pr*KLD + k8*8 + tg + 4];
            a[3] = Ps[(pr+8)*KLD + k8*8 + tg + 4];
            uint32_t vrow = vs_b + (((k8*16 + koV)*72) + doV) * 2;
#pragma unroll
            for (int dnp = 0; dnp < 4; dnp++) {
                uint32_t r0, r1, r2, r3;
                LDSM_X4_T(r0, r1, r2, r3, vrow + dnp*32);
                uint32_t b0[2] = {r0, r1}, b1[2] = {r2, r3};
                mma_f16(o[2*dnp],   a, b0);
                mma_f16(o[2*dnp+1], a, b1);
            }
        }
        __syncthreads();   // stage (kt&1) free for tile kt+2's prefetch
    }

    // finalize
    const float il1 = 1.0f / l1, il2 = 1.0f / l2;
    float* y1 = g_y + (size_t)(b*TT + rq1 - 0) * (NHh*HDd) + h*HDd;
    float* y2 = g_y + (size_t)(b*TT + rq1 + 8) * (NHh*HDd) + h*HDd;
#pragma unroll
    for (int dn = 0; dn < 8; dn++) {
        int cc = dn*8 + tg*2;
        *(float2*)(y1 + cc) = make_float2(o[dn][0]*il1, o[dn][1]*il1);
        *(float2*)(y2 + cc) = make_float2(o[dn][2]*il2, o[dn][3]*il2);
    }
}

// ---------------------------------------------------------------------------
extern "C" void kernel_launch(void* const* d_in, const int* in_sizes, int n_in,
                              void* d_out, int out_size)
{
    const float* x      = (const float*)d_in[0];
    const float* ve     = (const float*)d_in[1];
    const float* cosT   = (const float*)d_in[2];
    const float* sinT   = (const float*)d_in[3];
    const float* Wq     = (const float*)d_in[4];
    const float* Wk     = (const float*)d_in[5];
    const float* Wv     = (const float*)d_in[6];
    const float* Wproj  = (const float*)d_in[7];
    const float* Wg     = (const float*)d_in[8];
    const float* memk   = (const float*)d_in[9];
    const float* memv   = (const float*)d_in[10];
    const float* vscale = (const float*)d_in[11];
    float* out = (float*)d_out;

    void *p_qt, *p_kt, *p_vt, *p_y;
    cudaGetSymbolAddress(&p_qt, g_qt);
    cudaGetSymbolAddress(&p_kt, g_kt);
    cudaGetSymbolAddress(&p_vt, g_vt);
    cudaGetSymbolAddress(&p_y,  g_y);

    const int Mrows = BB * TT;   // 4096
    cudaFuncSetAttribute(attn_f16, cudaFuncAttributeMaxDynamicSharedMemorySize, ATTN_SMEM);

    // QKV projections (fp16 tensor cores, A hi/lo split)
    gemm_f16_nt<<<dim3(CCd/128, Mrows/128), 256>>>(x, Wq, (float*)p_qt, CCd, CCd);
    gemm_f16_nt<<<dim3((NKVh*HDd)/128, Mrows/128), 256>>>(x, Wk, (float*)p_kt, NKVh*HDd, CCd);
    gemm_f16_nt<<<dim3((NKVh*HDd)/128, Mrows/128), 256>>>(x, Wv, (float*)p_vt, NKVh*HDd, CCd);

    // RoPE + RMS + gate + memory concat -> fp16 Q/K/V
    {
        const int nwarps = BB*TT*NHh + BB*TT*NKVh + BB*TT*NKVh + BB*MMem*NKVh;  // 98816
        postproc<<<(nwarps * 32) / 256, 256>>>(x, ve, cosT, sinT, Wg, memk, memv, vscale);
    }

    // Flash attention (fp16 tensor cores, cp.async pipelined)
    attn_f16<<<dim3(TT/128, NHh, BB), 256, ATTN_SMEM>>>();

    // Output projection (fp16, A hi/lo split)
    gemm_f16_nt<<<dim3(CCd/128, Mrows/128), 256>>>((const float*)p_y, Wproj, out, CCd, CCd);
}

// round 9
// speedup vs baseline: 1.3280x; 1.3280x over previous
#include <cuda_runtime.h>
#include <cuda_fp16.h>
#include <math.h>
#include <stdint.h>

// Problem constants
#define BB    2
#define TT    2048
#define CCd   1024
#define NHh   16
#define NKVh  4
#define HDd   64
#define MMem  64
#define SSs   (MMem + TT)   // 2112

// Scratch (device globals; allocation-free per harness rules)
__device__ float  g_qt[BB*TT*NHh*HDd];    // QKV gemm outs: [B*T][1024]
__device__ float  g_kt[BB*TT*NKVh*HDd];   // [B*T][256]
__device__ float  g_vt[BB*TT*NKVh*HDd];   // [B*T][256]
__device__ __half g_qh[BB*NHh*TT*HDd];    // [b][h][t][d]   fp16
__device__ __half g_kh[BB*NKVh*SSs*HDd];  // [b][kv][s][d]  fp16
__device__ __half g_vh[BB*NKVh*SSs*HDd];  // [b][kv][s][d]  fp16
__device__ float  g_y [BB*TT*NHh*HDd];    // attn out [B*T][1024]

// ---------------------------------------------------------------------------
// fp16 helpers
// ---------------------------------------------------------------------------
__device__ __forceinline__ uint32_t h2u(__half2 h) { return *(uint32_t*)&h; }
__device__ __forceinline__ uint32_t packh(float a, float b) {
    __half2 t = __floats2half2_rn(a, b);
    return h2u(t);
}

__device__ __forceinline__ void mma_f16(float* c, const uint32_t* a, const uint32_t* b) {
    asm("mma.sync.aligned.m16n8k16.row.col.f32.f16.f16.f32 "
        "{%0,%1,%2,%3},{%4,%5,%6,%7},{%8,%9},{%0,%1,%2,%3};"
        : "+f"(c[0]), "+f"(c[1]), "+f"(c[2]), "+f"(c[3])
        : "r"(a[0]), "r"(a[1]), "r"(a[2]), "r"(a[3]), "r"(b[0]), "r"(b[1]));
}

#define LDSM_X4(r0,r1,r2,r3,addr) \
    asm volatile("ldmatrix.sync.aligned.m8n8.x4.shared.b16 {%0,%1,%2,%3}, [%4];" \
                 : "=r"(r0), "=r"(r1), "=r"(r2), "=r"(r3) : "r"(addr))
#define LDSM_X4_T(r0,r1,r2,r3,addr) \
    asm volatile("ldmatrix.sync.aligned.m8n8.x4.trans.shared.b16 {%0,%1,%2,%3}, [%4];" \
                 : "=r"(r0), "=r"(r1), "=r"(r2), "=r"(r3) : "r"(addr))

__device__ __forceinline__ uint32_t smem_u32(const void* p) {
    uint32_t a;
    asm("{ .reg .u64 t; cvta.to.shared.u64 t, %1; cvt.u32.u64 %0, t; }" : "=r"(a) : "l"(p));
    return a;
}

// ---------------------------------------------------------------------------
// fp16 NT GEMM; SPLIT adds an A-side hi/lo correction (near-fp32 A).
// C[m][n] = sum_k A[m][k]*Bw[n][k].  Block 128x128, K-tile 32, 8 warps 4x2.
// ---------------------------------------------------------------------------
#define GLD 20
template<bool SPLIT>
__global__ __launch_bounds__(256) void gemm_f16_nt(
    const float* __restrict__ A, const float* __restrict__ Bw,
    float* __restrict__ Cm, int N, int K)
{
    __shared__ uint32_t Ah[128*GLD];
    __shared__ uint32_t Al[128*GLD];
    __shared__ uint32_t Bs[128*GLD];
    const int tid = threadIdx.x;
    const int lane = tid & 31, wid = tid >> 5;
    const int wm = wid & 3, wn = wid >> 2;
    const int g = lane >> 2, tg = lane & 3;
    const int m0 = blockIdx.y * 128;
    const int n0 = blockIdx.x * 128;

    float acc[2][8][4] = {};

    for (int k0 = 0; k0 < K; k0 += 32) {
#pragma unroll
        for (int q = 0; q < 4; q++) {
            int idx = q * 256 + tid;
            int row = idx >> 3, kq = (idx & 7) * 4;
            float4 av = *(const float4*)(A + (size_t)(m0 + row) * K + k0 + kq);
            __half2 h0 = __floats2half2_rn(av.x, av.y);
            __half2 h1 = __floats2half2_rn(av.z, av.w);
            *(uint2*)&Ah[row*GLD + (kq >> 1)] = make_uint2(h2u(h0), h2u(h1));
            if (SPLIT) {
                float2 f0 = __half22float2(h0), f1 = __half22float2(h1);
                *(uint2*)&Al[row*GLD + (kq >> 1)] = make_uint2(
                    packh(av.x - f0.x, av.y - f0.y), packh(av.z - f1.x, av.w - f1.y));
            }
            float4 bv = *(const float4*)(Bw + (size_t)(n0 + row) * K + k0 + kq);
            *(uint2*)&Bs[row*GLD + (kq >> 1)] = make_uint2(
                packh(bv.x, bv.y), packh(bv.z, bv.w));
        }
        __syncthreads();
#pragma unroll
        for (int ks = 0; ks < 2; ks++) {
            const int kp = ks * 8;
            uint32_t ah[2][4], al[2][4], b[8][2];
#pragma unroll
            for (int am = 0; am < 2; am++) {
                int r = wm*32 + am*16 + g;
                ah[am][0] = Ah[r*GLD + kp + tg];
                ah[am][1] = Ah[(r+8)*GLD + kp + tg];
                ah[am][2] = Ah[r*GLD + kp + tg + 4];
                ah[am][3] = Ah[(r+8)*GLD + kp + tg + 4];
                if (SPLIT) {
                    al[am][0] = Al[r*GLD + kp + tg];
                    al[am][1] = Al[(r+8)*GLD + kp + tg];
                    al[am][2] = Al[r*GLD + kp + tg + 4];
                    al[am][3] = Al[(r+8)*GLD + kp + tg + 4];
                }
            }
#pragma unroll
            for (int an = 0; an < 8; an++) {
                int c = wn*64 + an*8 + g;
                b[an][0] = Bs[c*GLD + kp + tg];
                b[an][1] = Bs[c*GLD + kp + tg + 4];
            }
#pragma unroll
            for (int am = 0; am < 2; am++)
#pragma unroll
                for (int an = 0; an < 8; an++) {
                    mma_f16(acc[am][an], ah[am], b[an]);
                    if (SPLIT) mma_f16(acc[am][an], al[am], b[an]);
                }
        }
        __syncthreads();
    }

#pragma unroll
    for (int am = 0; am < 2; am++)
#pragma unroll
        for (int an = 0; an < 8; an++) {
            int r = m0 + wm*32 + am*16 + g;
            int cc = n0 + wn*64 + an*8 + tg*2;
            *(float2*)(Cm + (size_t)r*N + cc)     = make_float2(acc[am][an][0], acc[am][an][1]);
            *(float2*)(Cm + (size_t)(r+8)*N + cc) = make_float2(acc[am][an][2], acc[am][an][3]);
        }
}

// ---------------------------------------------------------------------------
// Postprocess -> fp16 Q/K/V (unchanged from R8)
// ---------------------------------------------------------------------------
__device__ __forceinline__ float warpsum32(float v) {
#pragma unroll
    for (int o = 16; o > 0; o >>= 1) v += __shfl_xor_sync(0xffffffffu, v, o);
    return v;
}

__global__ void postproc(const float* __restrict__ x,   const float* __restrict__ ve,
                         const float* __restrict__ cosT,const float* __restrict__ sinT,
                         const float* __restrict__ Wg,  const float* __restrict__ memk,
                         const float* __restrict__ memv,const float* __restrict__ vscale)
{
    const int gg   = blockIdx.x * blockDim.x + threadIdx.x;
    const int w    = gg >> 5;
    const int lane = gg & 31;
    const int NQ = BB*TT*NHh;
    const int NK = BB*TT*NKVh;
    const int NV = NK;

    if (w < NQ) {
        int h = w % NHh; int t = (w / NHh) % TT; int b = w / (NHh * TT);
        const float* src = g_qt + (size_t)(b*TT + t) * CCd + h * HDd;
        float x1 = src[lane], x2 = src[lane + 32];
        float c = cosT[t*32 + lane], s = sinT[t*32 + lane];
        float o1 = x1*c - x2*s, o2 = x1*s + x2*c;
        float ss = warpsum32(o1*o1 + o2*o2);
        float r = rsqrtf(ss * (1.0f/HDd) + 1e-6f) * 1.2f;
        __half* dst = g_qh + (size_t)((b*NHh + h)*TT + t) * HDd;
        dst[lane] = __float2half(o1*r); dst[lane + 32] = __float2half(o2*r);
    } else if (w < NQ + NK) {
        int w2 = w - NQ;
        int n = w2 % NKVh; int t = (w2 / NKVh) % TT; int b = w2 / (NKVh * TT);
        const float* src = g_kt + (size_t)(b*TT + t) * (NKVh*HDd) + n * HDd;
        float x1 = src[lane], x2 = src[lane + 32];
        float c = cosT[t*32 + lane], s = sinT[t*32 + lane];
        float o1 = x1*c - x2*s, o2 = x1*s + x2*c;
        float ss = warpsum32(o1*o1 + o2*o2);
        float r = rsqrtf(ss * (1.0f/HDd) + 1e-6f) * 1.2f;
        __half* dst = g_kh + (size_t)((b*NKVh + n)*SSs + (MMem + t)) * HDd;
        dst[lane] = __float2half(o1*r); dst[lane + 32] = __float2half(o2*r);
    } else if (w < NQ + NK + NV) {
        int w3 = w - NQ - NK;
        int n = w3 % NKVh; int t = (w3 / NKVh) % TT; int b = w3 / (NKVh * TT);
        float gp = x[(size_t)(b*TT + t)*CCd + lane] * Wg[n*32 + lane];
        float dot = warpsum32(gp);
        float gate = 3.0f / (1.0f + __expf(-dot));
        const float* src = g_vt + (size_t)(b*TT + t) * (NKVh*HDd) + n * HDd;
        const float* vep = ve  + (size_t)(b*TT + t) * (NKVh*HDd) + n * HDd;
        float o1 = src[lane]      + gate * vep[lane];
        float o2 = src[lane + 32] + gate * vep[lane + 32];
        __half* dst = g_vh + (size_t)((b*NKVh + n)*SSs + (MMem + t)) * HDd;
        dst[lane] = __float2half(o1); dst[lane + 32] = __float2half(o2);
    } else {
        int w4 = w - NQ - NK - NV;
        int n = w4 % NKVh; int j = (w4 / NKVh) % MMem; int b = w4 / (NKVh * MMem);
        const float* mkp = memk + (size_t)(j*NKVh + n) * HDd;
        float x1 = mkp[lane], x2 = mkp[lane + 32];
        float ss = warpsum32(x1*x1 + x2*x2);
        float r = rsqrtf(ss * (1.0f/HDd) + 1e-6f) * 1.2f;
        __half* kd = g_kh + (size_t)((b*NKVh + n)*SSs + j) * HDd;
        kd[lane] = __float2half(x1*r); kd[lane + 32] = __float2half(x2*r);
        const float* mvp = memv + (size_t)(j*NKVh + n) * HDd;
        float vs = vscale[0];
        __half* vd = g_vh + (size_t)((b*NKVh + n)*SSs + j) * HDd;
        vd[lane] = __float2half(mvp[lane] * vs); vd[lane + 32] = __float2half(mvp[lane + 32] * vs);
    }
}

// ---------------------------------------------------------------------------
// fp16 flash attention, 128-key tiles (halved per-tile softmax overhead).
// Block = 128 q-rows; 8 warps, each owns 16 q-rows x 128 keys.
// Single-stage K/V smem (pitch 144B, same LDSM addressing as R7/R8).
// Tiles per block: qi+2; mask needed for kt >= qi (kpos offset M=64).
// Dyn smem: K 18432 + V 18432 + Ps 34816 = 71680 B.
// ---------------------------------------------------------------------------
#define KLD 36   // u32 per K/V row = 144 B
#define PLD 68   // u32 per P row (128 keys = 64 u32 + 4 pad)
#define ATTN_SMEM ((2*128*KLD + 128*PLD) * 4)   // 71680

__global__ __launch_bounds__(256) void attn_f16()
{
    extern __shared__ uint32_t sm[];
    uint32_t* Ks = sm;
    uint32_t* Vs = sm + 128*KLD;
    uint32_t* Ps = sm + 2*128*KLD;

    const int tid = threadIdx.x;
    const int lane = tid & 31, wid = tid >> 5;
    const int g = lane >> 2, tg = lane & 3;
    const int qi = (int)(gridDim.x - 1 - blockIdx.x);   // long blocks first
    const int h = blockIdx.y, b = blockIdx.z;
    const int t0 = qi * 128;
    const int kvh = h >> 2;

    const __half* qptr = g_qh + (size_t)(b*NHh  + h  ) * TT  * HDd;
    const __half* kptr = g_kh + (size_t)(b*NKVh + kvh) * SSs * HDd;
    const __half* vptr = g_vh + (size_t)(b*NKVh + kvh) * SSs * HDd;

    const uint32_t ks_b = smem_u32(Ks);
    const uint32_t vs_b = smem_u32(Vs);

    // ldmatrix lane->address components (identical to R7/R8)
    const int koK = (lane & 7) + ((lane & 16) >> 1);
    const int doK = lane & 8;
    const int koV = lane & 15;
    const int doV = (lane & 16) >> 1;

    // Q fragments (fp16 gmem -> direct u32 loads)
    const int rq1 = t0 + wid*16 + g;
    uint32_t qa[4][4];
#pragma unroll
    for (int s8 = 0; s8 < 4; s8++) {
        int d0 = s8*16 + 2*tg;
        qa[s8][0] = *(const uint32_t*)(qptr + (size_t)rq1*HDd + d0);
        qa[s8][1] = *(const uint32_t*)(qptr + (size_t)(rq1+8)*HDd + d0);
        qa[s8][2] = *(const uint32_t*)(qptr + (size_t)rq1*HDd + d0 + 8);
        qa[s8][3] = *(const uint32_t*)(qptr + (size_t)(rq1+8)*HDd + d0 + 8);
    }

    float o[8][4] = {};
    float m1 = -INFINITY, m2 = -INFINITY, l1 = 0.0f, l2 = 0.0f;

    const int nkt = qi + 2;
    for (int kt = 0; kt < nkt; kt++) {
        __syncthreads();
        // load K/V tiles: 128 rows x 64 halfs each (clamped; overruns masked)
#pragma unroll
        for (int q = 0; q < 4; q++) {
            int idx = q * 256 + tid;
            int row = idx >> 3, c8 = idx & 7;
            int kr = kt*128 + row; if (kr > SSs - 1) kr = SSs - 1;
            *(uint4*)&Ks[row*KLD + c8*4] = *(const uint4*)(kptr + (size_t)kr*HDd + c8*8);
            *(uint4*)&Vs[row*KLD + c8*4] = *(const uint4*)(vptr + (size_t)kr*HDd + c8*8);
        }
        __syncthreads();

        // S = Q K^T : warp computes 16 rows x 128 keys
        float s[16][4] = {};
#pragma unroll
        for (int s8 = 0; s8 < 4; s8++) {
#pragma unroll
            for (int anp = 0; anp < 8; anp++) {
                uint32_t r0, r1, r2, r3;
                uint32_t addr = ks_b + (((anp*16 + koK)*72) + s8*16 + doK) * 2;
                LDSM_X4(r0, r1, r2, r3, addr);
                uint32_t b0[2] = {r0, r1}, b1[2] = {r2, r3};
                mma_f16(s[2*anp],   qa[s8], b0);
                mma_f16(s[2*anp+1], qa[s8], b1);
            }
        }

        // scale + causal mask (key seq pos = kt*128 + col - M)
        const bool dg = (kt >= qi);
#pragma unroll
        for (int an = 0; an < 16; an++) {
            int j0 = kt*128 + an*8 + tg*2 - MMem;
            s[an][0] *= 0.125f; s[an][1] *= 0.125f;
            s[an][2] *= 0.125f; s[an][3] *= 0.125f;
            if (dg) {
                if (j0     > rq1)   s[an][0] = -INFINITY;
                if (j0 + 1 > rq1)   s[an][1] = -INFINITY;
                if (j0     > rq1+8) s[an][2] = -INFINITY;
                if (j0 + 1 > rq1+8) s[an][3] = -INFINITY;
            }
        }

        // online softmax (one update per 128 keys)
        float tm1 = -INFINITY, tm2 = -INFINITY;
#pragma unroll
        for (int an = 0; an < 16; an++) {
            tm1 = fmaxf(tm1, fmaxf(s[an][0], s[an][1]));
            tm2 = fmaxf(tm2, fmaxf(s[an][2], s[an][3]));
        }
        tm1 = fmaxf(tm1, __shfl_xor_sync(0xffffffffu, tm1, 1));
        tm1 = fmaxf(tm1, __shfl_xor_sync(0xffffffffu, tm1, 2));
        tm2 = fmaxf(tm2, __shfl_xor_sync(0xffffffffu, tm2, 1));
        tm2 = fmaxf(tm2, __shfl_xor_sync(0xffffffffu, tm2, 2));

        float mn1 = fmaxf(m1, tm1), mn2 = fmaxf(m2, tm2);
        float sc1 = __expf(m1 - mn1), sc2 = __expf(m2 - mn2);
        m1 = mn1; m2 = mn2;
        l1 *= sc1; l2 *= sc2;
#pragma unroll
        for (int dn = 0; dn < 8; dn++) {
            o[dn][0] *= sc1; o[dn][1] *= sc1;
            o[dn][2] *= sc2; o[dn][3] *= sc2;
        }
        float rs1 = 0.0f, rs2 = 0.0f;
#pragma unroll
        for (int an = 0; an < 16; an++) {
            s[an][0] = __expf(s[an][0] - mn1); s[an][1] = __expf(s[an][1] - mn1);
            s[an][2] = __expf(s[an][2] - mn2); s[an][3] = __expf(s[an][3] - mn2);
            rs1 += s[an][0] + s[an][1];
            rs2 += s[an][2] + s[an][3];
        }
        rs1 += __shfl_xor_sync(0xffffffffu, rs1, 1);
        rs1 += __shfl_xor_sync(0xffffffffu, rs1, 2);
        rs2 += __shfl_xor_sync(0xffffffffu, rs2, 1);
        rs2 += __shfl_xor_sync(0xffffffffu, rs2, 2);
        l1 += rs1; l2 += rs2;

        // P -> warp-private smem rows (packed fp16x2 along keys)
        const int pr = wid*16 + g;
#pragma unroll
        for (int an = 0; an < 16; an++) {
            Ps[pr*PLD + an*4 + tg]     = packh(s[an][0], s[an][1]);
            Ps[(pr+8)*PLD + an*4 + tg] = packh(s[an][2], s[an][3]);
        }
        __syncwarp();

        // O += P V
#pragma unroll
        for (int k8 = 0; k8 < 8; k8++) {
            uint32_t a[4];
            a[0] = Ps[pr*PLD + k8*8 + tg];
            a[1] = Ps[(pr+8)*PLD + k8*8 + tg];
            a[2] = Ps[pr*PLD + k8*8 + tg + 4];
            a[3] = Ps[(pr+8)*PLD + k8*8 + tg + 4];
            uint32_t vrow = vs_b + (((k8*16 + koV)*72) + doV) * 2;
#pragma unroll
            for (int dnp = 0; dnp < 4; dnp++) {
                uint32_t r0, r1, r2, r3;
                LDSM_X4_T(r0, r1, r2, r3, vrow + dnp*32);
                uint32_t b0[2] = {r0, r1}, b1[2] = {r2, r3};
                mma_f16(o[2*dnp],   a, b0);
                mma_f16(o[2*dnp+1], a, b1);
            }
        }
    }

    // finalize
    const float il1 = 1.0f / l1, il2 = 1.0f / l2;
    float* y1 = g_y + (size_t)(b*TT + rq1 - 0) * (NHh*HDd) + h*HDd;
    float* y2 = g_y + (size_t)(b*TT + rq1 + 8) * (NHh*HDd) + h*HDd;
#pragma unroll
    for (int dn = 0; dn < 8; dn++) {
        int cc = dn*8 + tg*2;
        *(float2*)(y1 + cc) = make_float2(o[dn][0]*il1, o[dn][1]*il1);
        *(float2*)(y2 + cc) = make_float2(o[dn][2]*il2, o[dn][3]*il2);
    }
}

// ---------------------------------------------------------------------------
extern "C" void kernel_launch(void* const* d_in, const int* in_sizes, int n_in,
                              void* d_out, int out_size)
{
    const float* x      = (const float*)d_in[0];
    const float* ve     = (const float*)d_in[1];
    const float* cosT   = (const float*)d_in[2];
    const float* sinT   = (const float*)d_in[3];
    const float* Wq     = (const float*)d_in[4];
    const float* Wk     = (const float*)d_in[5];
    const float* Wv     = (const float*)d_in[6];
    const float* Wproj  = (const float*)d_in[7];
    const float* Wg     = (const float*)d_in[8];
    const float* memk   = (const float*)d_in[9];
    const float* memv   = (const float*)d_in[10];
    const float* vscale = (const float*)d_in[11];
    float* out = (float*)d_out;

    void *p_qt, *p_kt, *p_vt, *p_y;
    cudaGetSymbolAddress(&p_qt, g_qt);
    cudaGetSymbolAddress(&p_kt, g_kt);
    cudaGetSymbolAddress(&p_vt, g_vt);
    cudaGetSymbolAddress(&p_y,  g_y);

    const int Mrows = BB * TT;   // 4096
    cudaFuncSetAttribute(attn_f16, cudaFuncAttributeMaxDynamicSharedMemorySize, ATTN_SMEM);

    // QKV projections (plain fp16 tensor cores)
    gemm_f16_nt<false><<<dim3(CCd/128, Mrows/128), 256>>>(x, Wq, (float*)p_qt, CCd, CCd);
    gemm_f16_nt<false><<<dim3((NKVh*HDd)/128, Mrows/128), 256>>>(x, Wk, (float*)p_kt, NKVh*HDd, CCd);
    gemm_f16_nt<false><<<dim3((NKVh*HDd)/128, Mrows/128), 256>>>(x, Wv, (float*)p_vt, NKVh*HDd, CCd);

    // RoPE + RMS + gate + memory concat -> fp16 Q/K/V
    {
        const int nwarps = BB*TT*NHh + BB*TT*NKVh + BB*TT*NKVh + BB*MMem*NKVh;  // 98816
        postproc<<<(nwarps * 32) / 256, 256>>>(x, ve, cosT, sinT, Wg, memk, memv, vscale);
    }

    // Flash attention (fp16, 128-key tiles)
    attn_f16<<<dim3(TT/128, NHh, BB), 256, ATTN_SMEM>>>();

    // Output projection (fp16 with A hi/lo split for near-fp32 output precision)
    gemm_f16_nt<true><<<dim3(CCd/128, Mrows/128), 256>>>((const float*)p_y, Wproj, out, CCd, CCd);
}

// round 12
// speedup vs baseline: 1.5406x; 1.1601x over previous
#include <cuda_runtime.h>
#include <cuda_fp16.h>
#include <math.h>
#include <stdint.h>

// Problem constants
#define BB    2
#define TT    2048
#define CCd   1024
#define NHh   16
#define NKVh  4
#define HDd   64
#define MMem  64
#define SSs   (MMem + TT)   // 2112

// Scratch (device globals; allocation-free per harness rules)
__device__ float  g_qt[BB*TT*NHh*HDd];    // QKV gemm outs: [B*T][1024]
__device__ float  g_kt[BB*TT*NKVh*HDd];   // [B*T][256]
__device__ float  g_vt[BB*TT*NKVh*HDd];   // [B*T][256]
__device__ __half g_qh[BB*NHh*TT*HDd];    // [b][h][t][d]   fp16
__device__ __half g_kh[BB*NKVh*SSs*HDd];  // [b][kv][s][d]  fp16
__device__ __half g_vh[BB*NKVh*SSs*HDd];  // [b][kv][s][d]  fp16
__device__ float  g_y [BB*TT*NHh*HDd];    // attn out [B*T][1024]

// ---------------------------------------------------------------------------
// fp16 helpers
// ---------------------------------------------------------------------------
__device__ __forceinline__ uint32_t h2u(__half2 h) { return *(uint32_t*)&h; }
__device__ __forceinline__ uint32_t packh(float a, float b) {
    __half2 t = __floats2half2_rn(a, b);
    return h2u(t);
}

__device__ __forceinline__ void mma_f16(float* c, const uint32_t* a, const uint32_t* b) {
    asm("mma.sync.aligned.m16n8k16.row.col.f32.f16.f16.f32 "
        "{%0,%1,%2,%3},{%4,%5,%6,%7},{%8,%9},{%0,%1,%2,%3};"
        : "+f"(c[0]), "+f"(c[1]), "+f"(c[2]), "+f"(c[3])
        : "r"(a[0]), "r"(a[1]), "r"(a[2]), "r"(a[3]), "r"(b[0]), "r"(b[1]));
}

#define LDSM_X4(r0,r1,r2,r3,addr) \
    asm volatile("ldmatrix.sync.aligned.m8n8.x4.shared.b16 {%0,%1,%2,%3}, [%4];" \
                 : "=r"(r0), "=r"(r1), "=r"(r2), "=r"(r3) : "r"(addr))
#define LDSM_X4_T(r0,r1,r2,r3,addr) \
    asm volatile("ldmatrix.sync.aligned.m8n8.x4.trans.shared.b16 {%0,%1,%2,%3}, [%4];" \
                 : "=r"(r0), "=r"(r1), "=r"(r2), "=r"(r3) : "r"(addr))

__device__ __forceinline__ uint32_t smem_u32(const void* p) {
    uint32_t a;
    asm("{ .reg .u64 t; cvta.to.shared.u64 t, %1; cvt.u32.u64 %0, t; }" : "=r"(a) : "l"(p));
    return a;
}

// ---------------------------------------------------------------------------
// GEMM body (shared by fused-QKV and Wproj kernels).
// C[m][n] = sum_k A[m][k]*Bw[n][k].  Block 128x128, K-tile 32, 8 warps 4x2.
// SPLIT adds A-side hi/lo correction (near-fp32 A) — used for Wproj only.
// ---------------------------------------------------------------------------
#define GLD 20
template<bool SPLIT>
__device__ __forceinline__ void gemm_body(
    const float* __restrict__ A, const float* __restrict__ Bw,
    float* __restrict__ Cm, int N, int K, int m0, int n0,
    uint32_t* Ah, uint32_t* Al, uint32_t* Bs)
{
    const int tid = threadIdx.x;
    const int lane = tid & 31, wid = tid >> 5;
    const int wm = wid & 3, wn = wid >> 2;
    const int g = lane >> 2, tg = lane & 3;

    float acc[2][8][4] = {};

    for (int k0 = 0; k0 < K; k0 += 32) {
#pragma unroll
        for (int q = 0; q < 4; q++) {
            int idx = q * 256 + tid;
            int row = idx >> 3, kq = (idx & 7) * 4;
            float4 av = *(const float4*)(A + (size_t)(m0 + row) * K + k0 + kq);
            __half2 h0 = __floats2half2_rn(av.x, av.y);
            __half2 h1 = __floats2half2_rn(av.z, av.w);
            *(uint2*)&Ah[row*GLD + (kq >> 1)] = make_uint2(h2u(h0), h2u(h1));
            if (SPLIT) {
                float2 f0 = __half22float2(h0), f1 = __half22float2(h1);
                *(uint2*)&Al[row*GLD + (kq >> 1)] = make_uint2(
                    packh(av.x - f0.x, av.y - f0.y), packh(av.z - f1.x, av.w - f1.y));
            }
            float4 bv = *(const float4*)(Bw + (size_t)(n0 + row) * K + k0 + kq);
            *(uint2*)&Bs[row*GLD + (kq >> 1)] = make_uint2(
                packh(bv.x, bv.y), packh(bv.z, bv.w));
        }
        __syncthreads();
#pragma unroll
        for (int ks = 0; ks < 2; ks++) {
            const int kp = ks * 8;
            uint32_t ah[2][4], al[2][4], b[8][2];
#pragma unroll
            for (int am = 0; am < 2; am++) {
                int r = wm*32 + am*16 + g;
                ah[am][0] = Ah[r*GLD + kp + tg];
                ah[am][1] = Ah[(r+8)*GLD + kp + tg];
                ah[am][2] = Ah[r*GLD + kp + tg + 4];
                ah[am][3] = Ah[(r+8)*GLD + kp + tg + 4];
                if (SPLIT) {
                    al[am][0] = Al[r*GLD + kp + tg];
                    al[am][1] = Al[(r+8)*GLD + kp + tg];
                    al[am][2] = Al[r*GLD + kp + tg + 4];
                    al[am][3] = Al[(r+8)*GLD + kp + tg + 4];
                }
            }
#pragma unroll
            for (int an = 0; an < 8; an++) {
                int c = wn*64 + an*8 + g;
                b[an][0] = Bs[c*GLD + kp + tg];
                b[an][1] = Bs[c*GLD + kp + tg + 4];
            }
#pragma unroll
            for (int am = 0; am < 2; am++)
#pragma unroll
                for (int an = 0; an < 8; an++) {
                    mma_f16(acc[am][an], ah[am], b[an]);
                    if (SPLIT) mma_f16(acc[am][an], al[am], b[an]);
                }
        }
        __syncthreads();
    }

#pragma unroll
    for (int am = 0; am < 2; am++)
#pragma unroll
        for (int an = 0; an < 8; an++) {
            int r = m0 + wm*32 + am*16 + g;
            int cc = n0 + wn*64 + an*8 + tg*2;
            *(float2*)(Cm + (size_t)r*N + cc)     = make_float2(acc[am][an][0], acc[am][an][1]);
            *(float2*)(Cm + (size_t)(r+8)*N + cc) = make_float2(acc[am][an][2], acc[am][an][3]);
        }
}

// Fused QKV: grid.x = 12 -> 8 Q n-tiles, 2 K, 2 V. One full-occupancy launch.
__global__ __launch_bounds__(256) void gemm_qkv(
    const float* __restrict__ x,
    const float* __restrict__ Wq, const float* __restrict__ Wk,
    const float* __restrict__ Wv,
    float* __restrict__ qt, float* __restrict__ kt, float* __restrict__ vt)
{
    __shared__ uint32_t Ah[128*GLD];
    __shared__ uint32_t Bs[128*GLD];
    const int bx = blockIdx.x;
    const int m0 = blockIdx.y * 128;
    const float* Bw; float* Cm; int N, n0;
    if (bx < 8)       { Bw = Wq; Cm = qt; N = CCd;       n0 = bx*128; }
    else if (bx < 10) { Bw = Wk; Cm = kt; N = NKVh*HDd;  n0 = (bx-8)*128; }
    else              { Bw = Wv; Cm = vt; N = NKVh*HDd;  n0 = (bx-10)*128; }
    gemm_body<false>(x, Bw, Cm, N, CCd, m0, n0, Ah, nullptr, Bs);
}

// Wproj with hi/lo split (near-fp32 output precision)
__global__ __launch_bounds__(256) void gemm_proj(
    const float* __restrict__ A, const float* __restrict__ Bw,
    float* __restrict__ Cm)
{
    __shared__ uint32_t Ah[128*GLD];
    __shared__ uint32_t Al[128*GLD];
    __shared__ uint32_t Bs[128*GLD];
    gemm_body<true>(A, Bw, Cm, CCd, CCd, blockIdx.y*128, blockIdx.x*128, Ah, Al, Bs);
}

// ---------------------------------------------------------------------------
// Postprocess -> fp16 Q/K/V (unchanged)
// ---------------------------------------------------------------------------
__device__ __forceinline__ float warpsum32(float v) {
#pragma unroll
    for (int o = 16; o > 0; o >>= 1) v += __shfl_xor_sync(0xffffffffu, v, o);
    return v;
}

__global__ void postproc(const float* __restrict__ x,   const float* __restrict__ ve,
                         const float* __restrict__ cosT,const float* __restrict__ sinT,
                         const float* __restrict__ Wg,  const float* __restrict__ memk,
                         const float* __restrict__ memv,const float* __restrict__ vscale)
{
    const int gg   = blockIdx.x * blockDim.x + threadIdx.x;
    const int w    = gg >> 5;
    const int lane = gg & 31;
    const int NQ = BB*TT*NHh;
    const int NK = BB*TT*NKVh;
    const int NV = NK;

    if (w < NQ) {
        int h = w % NHh; int t = (w / NHh) % TT; int b = w / (NHh * TT);
        const float* src = g_qt + (size_t)(b*TT + t) * CCd + h * HDd;
        float x1 = src[lane], x2 = src[lane + 32];
        float c = cosT[t*32 + lane], s = sinT[t*32 + lane];
        float o1 = x1*c - x2*s, o2 = x1*s + x2*c;
        float ss = warpsum32(o1*o1 + o2*o2);
        float r = rsqrtf(ss * (1.0f/HDd) + 1e-6f) * 1.2f;
        __half* dst = g_qh + (size_t)((b*NHh + h)*TT + t) * HDd;
        dst[lane] = __float2half(o1*r); dst[lane + 32] = __float2half(o2*r);
    } else if (w < NQ + NK) {
        int w2 = w - NQ;
        int n = w2 % NKVh; int t = (w2 / NKVh) % TT; int b = w2 / (NKVh * TT);
        const float* src = g_kt + (size_t)(b*TT + t) * (NKVh*HDd) + n * HDd;
        float x1 = src[lane], x2 = src[lane + 32];
        float c = cosT[t*32 + lane], s = sinT[t*32 + lane];
        float o1 = x1*c - x2*s, o2 = x1*s + x2*c;
        float ss = warpsum32(o1*o1 + o2*o2);
        float r = rsqrtf(ss * (1.0f/HDd) + 1e-6f) * 1.2f;
        __half* dst = g_kh + (size_t)((b*NKVh + n)*SSs + (MMem + t)) * HDd;
        dst[lane] = __float2half(o1*r); dst[lane + 32] = __float2half(o2*r);
    } else if (w < NQ + NK + NV) {
        int w3 = w - NQ - NK;
        int n = w3 % NKVh; int t = (w3 / NKVh) % TT; int b = w3 / (NKVh * TT);
        float gp = x[(size_t)(b*TT + t)*CCd + lane] * Wg[n*32 + lane];
        float dot = warpsum32(gp);
        float gate = 3.0f / (1.0f + __expf(-dot));
        const float* src = g_vt + (size_t)(b*TT + t) * (NKVh*HDd) + n * HDd;
        const float* vep = ve  + (size_t)(b*TT + t) * (NKVh*HDd) + n * HDd;
        float o1 = src[lane]      + gate * vep[lane];
        float o2 = src[lane + 32] + gate * vep[lane + 32];
        __half* dst = g_vh + (size_t)((b*NKVh + n)*SSs + (MMem + t)) * HDd;
        dst[lane] = __float2half(o1); dst[lane + 32] = __float2half(o2);
    } else {
        int w4 = w - NQ - NK - NV;
        int n = w4 % NKVh; int j = (w4 / NKVh) % MMem; int b = w4 / (NKVh * MMem);
        const float* mkp = memk + (size_t)(j*NKVh + n) * HDd;
        float x1 = mkp[lane], x2 = mkp[lane + 32];
        float ss = warpsum32(x1*x1 + x2*x2);
        float r = rsqrtf(ss * (1.0f/HDd) + 1e-6f) * 1.2f;
        __half* kd = g_kh + (size_t)((b*NKVh + n)*SSs + j) * HDd;
        kd[lane] = __float2half(x1*r); kd[lane + 32] = __float2half(x2*r);
        const float* mvp = memv + (size_t)(j*NKVh + n) * HDd;
        float vs = vscale[0];
        __half* vd = g_vh + (size_t)((b*NKVh + n)*SSs + j) * HDd;
        vd[lane] = __float2half(mvp[lane] * vs); vd[lane + 32] = __float2half(mvp[lane + 32] * vs);
    }
}

// ---------------------------------------------------------------------------
// fp16 flash attention, 128-key tiles, synchronous K/V loads (proven R9
// loader), P kept in registers (C-frag of S == A-frag for PV, m16n8k16).
// Dyn smem: K 18432 + V 18432 = 36864 B -> 2 CTAs/SM.
// ---------------------------------------------------------------------------
#define KLD 36   // u32 per K/V row = 144 B
#define ATTN_SMEM (2*128*KLD*4)   // 36864 B

__global__ __launch_bounds__(256) void attn_f16()
{
    extern __shared__ uint32_t sm[];
    uint32_t* Ks = sm;
    uint32_t* Vs = sm + 128*KLD;

    const int tid = threadIdx.x;
    const int lane = tid & 31, wid = tid >> 5;
    const int g = lane >> 2, tg = lane & 3;
    const int qi = (int)(gridDim.x - 1 - blockIdx.x);   // long blocks first
    const int h = blockIdx.y, b = blockIdx.z;
    const int t0 = qi * 128;
    const int kvh = h >> 2;

    const __half* qptr = g_qh + (size_t)(b*NHh  + h  ) * TT  * HDd;
    const __half* kptr = g_kh + (size_t)(b*NKVh + kvh) * SSs * HDd;
    const __half* vptr = g_vh + (size_t)(b*NKVh + kvh) * SSs * HDd;

    const uint32_t ks_b = smem_u32(Ks);
    const uint32_t vs_b = smem_u32(Vs);

    // ldmatrix lane->address components (identical to R7-R9)
    const int koK = (lane & 7) + ((lane & 16) >> 1);
    const int doK = lane & 8;
    const int koV = lane & 15;
    const int doV = (lane & 16) >> 1;

    // Q fragments (fp16 gmem -> direct u32 loads)
    const int rq1 = t0 + wid*16 + g;
    uint32_t qa[4][4];
#pragma unroll
    for (int s8 = 0; s8 < 4; s8++) {
        int d0 = s8*16 + 2*tg;
        qa[s8][0] = *(const uint32_t*)(qptr + (size_t)rq1*HDd + d0);
        qa[s8][1] = *(const uint32_t*)(qptr + (size_t)(rq1+8)*HDd + d0);
        qa[s8][2] = *(const uint32_t*)(qptr + (size_t)rq1*HDd + d0 + 8);
        qa[s8][3] = *(const uint32_t*)(qptr + (size_t)(rq1+8)*HDd + d0 + 8);
    }

    float o[8][4] = {};
    float m1 = -INFINITY, m2 = -INFINITY, l1 = 0.0f, l2 = 0.0f;

    const int nkt = qi + 2;
    for (int kt = 0; kt < nkt; kt++) {
        __syncthreads();
        // load K/V tiles: 128 rows x 64 halfs each (clamped; overruns masked)
#pragma unroll
        for (int q = 0; q < 4; q++) {
            int idx = q * 256 + tid;
            int row = idx >> 3, c8 = idx & 7;
            int kr = kt*128 + row; if (kr > SSs - 1) kr = SSs - 1;
            *(uint4*)&Ks[row*KLD + c8*4] = *(const uint4*)(kptr + (size_t)kr*HDd + c8*8);
            *(uint4*)&Vs[row*KLD + c8*4] = *(const uint4*)(vptr + (size_t)kr*HDd + c8*8);
        }
        __syncthreads();

        // S = Q K^T : warp computes 16 rows x 128 keys
        float s[16][4] = {};
#pragma unroll
        for (int s8 = 0; s8 < 4; s8++) {
#pragma unroll
            for (int anp = 0; anp < 8; anp++) {
                uint32_t r0, r1, r2, r3;
                uint32_t addr = ks_b + (((anp*16 + koK)*72) + s8*16 + doK) * 2;
                LDSM_X4(r0, r1, r2, r3, addr);
                uint32_t b0[2] = {r0, r1}, b1[2] = {r2, r3};
                mma_f16(s[2*anp],   qa[s8], b0);
                mma_f16(s[2*anp+1], qa[s8], b1);
            }
        }

        // scale + causal mask (key seq pos = kt*128 + col - M)
        const bool dg = (kt >= qi);
#pragma unroll
        for (int an = 0; an < 16; an++) {
            int j0 = kt*128 + an*8 + tg*2 - MMem;
            s[an][0] *= 0.125f; s[an][1] *= 0.125f;
            s[an][2] *= 0.125f; s[an][3] *= 0.125f;
            if (dg) {
                if (j0     > rq1)   s[an][0] = -INFINITY;
                if (j0 + 1 > rq1)   s[an][1] = -INFINITY;
                if (j0     > rq1+8) s[an][2] = -INFINITY;
                if (j0 + 1 > rq1+8) s[an][3] = -INFINITY;
            }
        }

        // online softmax
        float tm1 = -INFINITY, tm2 = -INFINITY;
#pragma unroll
        for (int an = 0; an < 16; an++) {
            tm1 = fmaxf(tm1, fmaxf(s[an][0], s[an][1]));
            tm2 = fmaxf(tm2, fmaxf(s[an][2], s[an][3]));
        }
        tm1 = fmaxf(tm1, __shfl_xor_sync(0xffffffffu, tm1, 1));
        tm1 = fmaxf(tm1, __shfl_xor_sync(0xffffffffu, tm1, 2));
        tm2 = fmaxf(tm2, __shfl_xor_sync(0xffffffffu, tm2, 1));
        tm2 = fmaxf(tm2, __shfl_xor_sync(0xffffffffu, tm2, 2));

        float mn1 = fmaxf(m1, tm1), mn2 = fmaxf(m2, tm2);
        float sc1 = __expf(m1 - mn1), sc2 = __expf(m2 - mn2);
        m1 = mn1; m2 = mn2;
        l1 *= sc1; l2 *= sc2;
#pragma unroll
        for (int dn = 0; dn < 8; dn++) {
            o[dn][0] *= sc1; o[dn][1] *= sc1;
            o[dn][2] *= sc2; o[dn][3] *= sc2;
        }
        float rs1 = 0.0f, rs2 = 0.0f;
#pragma unroll
        for (int an = 0; an < 16; an++) {
            s[an][0] = __expf(s[an][0] - mn1); s[an][1] = __expf(s[an][1] - mn1);
            s[an][2] = __expf(s[an][2] - mn2); s[an][3] = __expf(s[an][3] - mn2);
            rs1 += s[an][0] + s[an][1];
            rs2 += s[an][2] + s[an][3];
        }
        rs1 += __shfl_xor_sync(0xffffffffu, rs1, 1);
        rs1 += __shfl_xor_sync(0xffffffffu, rs1, 2);
        rs2 += __shfl_xor_sync(0xffffffffu, rs2, 1);
        rs2 += __shfl_xor_sync(0xffffffffu, rs2, 2);
        l1 += rs1; l2 += rs2;

        // O += P V  — P taken straight from the S C-fragments (no smem!)
#pragma unroll
        for (int k8 = 0; k8 < 8; k8++) {
            uint32_t a[4];
            a[0] = packh(s[2*k8][0],   s[2*k8][1]);
            a[1] = packh(s[2*k8][2],   s[2*k8][3]);
            a[2] = packh(s[2*k8+1][0], s[2*k8+1][1]);
            a[3] = packh(s[2*k8+1][2], s[2*k8+1][3]);
            uint32_t vrow = vs_b + (((k8*16 + koV)*72) + doV) * 2;
#pragma unroll
            for (int dnp = 0; dnp < 4; dnp++) {
                uint32_t r0, r1, r2, r3;
                LDSM_X4_T(r0, r1, r2, r3, vrow + dnp*32);
                uint32_t b0[2] = {r0, r1}, b1[2] = {r2, r3};
                mma_f16(o[2*dnp],   a, b0);
                mma_f16(o[2*dnp+1], a, b1);
            }
        }
    }

    // finalize
    const float il1 = 1.0f / l1, il2 = 1.0f / l2;
    float* y1 = g_y + (size_t)(b*TT + rq1 - 0) * (NHh*HDd) + h*HDd;
    float* y2 = g_y + (size_t)(b*TT + rq1 + 8) * (NHh*HDd) + h*HDd;
#pragma unroll
    for (int dn = 0; dn < 8; dn++) {
        int cc = dn*8 + tg*2;
        *(float2*)(y1 + cc) = make_float2(o[dn][0]*il1, o[dn][1]*il1);
        *(float2*)(y2 + cc) = make_float2(o[dn][2]*il2, o[dn][3]*il2);
    }
}

// ---------------------------------------------------------------------------
extern "C" void kernel_launch(void* const* d_in, const int* in_sizes, int n_in,
                              void* d_out, int out_size)
{
    const float* x      = (const float*)d_in[0];
    const float* ve     = (const float*)d_in[1];
    const float* cosT   = (const float*)d_in[2];
    const float* sinT   = (const float*)d_in[3];
    const float* Wq     = (const float*)d_in[4];
    const float* Wk     = (const float*)d_in[5];
    const float* Wv     = (const float*)d_in[6];
    const float* Wproj  = (const float*)d_in[7];
    const float* Wg     = (const float*)d_in[8];
    const float* memk   = (const float*)d_in[9];
    const float* memv   = (const float*)d_in[10];
    const float* vscale = (const float*)d_in[11];
    float* out = (float*)d_out;

    void *p_qt, *p_kt, *p_vt, *p_y;
    cudaGetSymbolAddress(&p_qt, g_qt);
    cudaGetSymbolAddress(&p_kt, g_kt);
    cudaGetSymbolAddress(&p_vt, g_vt);
    cudaGetSymbolAddress(&p_y,  g_y);

    const int Mrows = BB * TT;   // 4096
    cudaFuncSetAttribute(attn_f16, cudaFuncAttributeMaxDynamicSharedMemorySize, ATTN_SMEM);

    // Fused QKV projections: one launch, 12x32 = 384 blocks
    gemm_qkv<<<dim3(12, Mrows/128), 256>>>(x, Wq, Wk, Wv,
                                           (float*)p_qt, (float*)p_kt, (float*)p_vt);

    // RoPE + RMS + gate + memory concat -> fp16 Q/K/V
    {
        const int nwarps = BB*TT*NHh + BB*TT*NKVh + BB*TT*NKVh + BB*MMem*NKVh;  // 98816
        postproc<<<(nwarps * 32) / 256, 256>>>(x, ve, cosT, sinT, Wg, memk, memv, vscale);
    }

    // Flash attention (fp16, 128-key tiles, P-in-regs)
    attn_f16<<<dim3(TT/128, NHh, BB), 256, ATTN_SMEM>>>();

    // Output projection (fp16 with A hi/lo split)
    gemm_proj<<<dim3(CCd/128, Mrows/128), 256>>>((const float*)p_y, Wproj, out);
}

// round 13
// speedup vs baseline: 1.6219x; 1.0528x over previous
#include <cuda_runtime.h>
#include <cuda_fp16.h>
#include <math.h>
#include <stdint.h>

// Problem constants
#define BB    2
#define TT    2048
#define CCd   1024
#define NHh   16
#define NKVh  4
#define HDd   64
#define MMem  64
#define SSs   (MMem + TT)   // 2112

// Scratch (device globals; allocation-free per harness rules)
__device__ float  g_qt[BB*TT*NHh*HDd];    // QKV gemm outs: [B*T][1024]
__device__ float  g_kt[BB*TT*NKVh*HDd];   // [B*T][256]
__device__ float  g_vt[BB*TT*NKVh*HDd];   // [B*T][256]
__device__ __half g_qh[BB*NHh*TT*HDd];    // [b][h][t][d]   fp16
__device__ __half g_kh[BB*NKVh*SSs*HDd];  // [b][kv][s][d]  fp16
__device__ __half g_vh[BB*NKVh*SSs*HDd];  // [b][kv][s][d]  fp16
__device__ float  g_y [BB*TT*NHh*HDd];    // attn out [B*T][1024]

// ---------------------------------------------------------------------------
// fp16 helpers
// ---------------------------------------------------------------------------
__device__ __forceinline__ uint32_t h2u(__half2 h) { return *(uint32_t*)&h; }
__device__ __forceinline__ uint32_t packh(float a, float b) {
    __half2 t = __floats2half2_rn(a, b);
    return h2u(t);
}

__device__ __forceinline__ void mma_f16(float* c, const uint32_t* a, const uint32_t* b) {
    asm("mma.sync.aligned.m16n8k16.row.col.f32.f16.f16.f32 "
        "{%0,%1,%2,%3},{%4,%5,%6,%7},{%8,%9},{%0,%1,%2,%3};"
        : "+f"(c[0]), "+f"(c[1]), "+f"(c[2]), "+f"(c[3])
        : "r"(a[0]), "r"(a[1]), "r"(a[2]), "r"(a[3]), "r"(b[0]), "r"(b[1]));
}

#define LDSM_X4(r0,r1,r2,r3,addr) \
    asm volatile("ldmatrix.sync.aligned.m8n8.x4.shared.b16 {%0,%1,%2,%3}, [%4];" \
                 : "=r"(r0), "=r"(r1), "=r"(r2), "=r"(r3) : "r"(addr))
#define LDSM_X4_T(r0,r1,r2,r3,addr) \
    asm volatile("ldmatrix.sync.aligned.m8n8.x4.trans.shared.b16 {%0,%1,%2,%3}, [%4];" \
                 : "=r"(r0), "=r"(r1), "=r"(r2), "=r"(r3) : "r"(addr))

__device__ __forceinline__ uint32_t smem_u32(const void* p) {
    uint32_t a;
    asm("{ .reg .u64 t; cvta.to.shared.u64 t, %1; cvt.u32.u64 %0, t; }" : "=r"(a) : "l"(p));
    return a;
}

// ---------------------------------------------------------------------------
// GEMM body (shared by fused-QKV and Wproj kernels).
// C[m][n] = sum_k A[m][k]*Bw[n][k].  Block 128x128, K-tile 32, 8 warps 4x2.
// SPLIT adds A-side hi/lo correction (near-fp32 A) — used for Wproj only.
// ---------------------------------------------------------------------------
#define GLD 20
template<bool SPLIT>
__device__ __forceinline__ void gemm_body(
    const float* __restrict__ A, const float* __restrict__ Bw,
    float* __restrict__ Cm, int N, int K, int m0, int n0,
    uint32_t* Ah, uint32_t* Al, uint32_t* Bs)
{
    const int tid = threadIdx.x;
    const int lane = tid & 31, wid = tid >> 5;
    const int wm = wid & 3, wn = wid >> 2;
    const int g = lane >> 2, tg = lane & 3;

    float acc[2][8][4] = {};

    for (int k0 = 0; k0 < K; k0 += 32) {
#pragma unroll
        for (int q = 0; q < 4; q++) {
            int idx = q * 256 + tid;
            int row = idx >> 3, kq = (idx & 7) * 4;
            float4 av = *(const float4*)(A + (size_t)(m0 + row) * K + k0 + kq);
            __half2 h0 = __floats2half2_rn(av.x, av.y);
            __half2 h1 = __floats2half2_rn(av.z, av.w);
            *(uint2*)&Ah[row*GLD + (kq >> 1)] = make_uint2(h2u(h0), h2u(h1));
            if (SPLIT) {
                float2 f0 = __half22float2(h0), f1 = __half22float2(h1);
                *(uint2*)&Al[row*GLD + (kq >> 1)] = make_uint2(
                    packh(av.x - f0.x, av.y - f0.y), packh(av.z - f1.x, av.w - f1.y));
            }
            float4 bv = *(const float4*)(Bw + (size_t)(n0 + row) * K + k0 + kq);
            *(uint2*)&Bs[row*GLD + (kq >> 1)] = make_uint2(
                packh(bv.x, bv.y), packh(bv.z, bv.w));
        }
        __syncthreads();
#pragma unroll
        for (int ks = 0; ks < 2; ks++) {
            const int kp = ks * 8;
            uint32_t ah[2][4], al[2][4], b[8][2];
#pragma unroll
            for (int am = 0; am < 2; am++) {
                int r = wm*32 + am*16 + g;
                ah[am][0] = Ah[r*GLD + kp + tg];
                ah[am][1] = Ah[(r+8)*GLD + kp + tg];
                ah[am][2] = Ah[r*GLD + kp + tg + 4];
                ah[am][3] = Ah[(r+8)*GLD + kp + tg + 4];
                if (SPLIT) {
                    al[am][0] = Al[r*GLD + kp + tg];
                    al[am][1] = Al[(r+8)*GLD + kp + tg];
                    al[am][2] = Al[r*GLD + kp + tg + 4];
                    al[am][3] = Al[(r+8)*GLD + kp + tg + 4];
                }
            }
#pragma unroll
            for (int an = 0; an < 8; an++) {
                int c = wn*64 + an*8 + g;
                b[an][0] = Bs[c*GLD + kp + tg];
                b[an][1] = Bs[c*GLD + kp + tg + 4];
            }
#pragma unroll
            for (int am = 0; am < 2; am++)
#pragma unroll
                for (int an = 0; an < 8; an++) {
                    mma_f16(acc[am][an], ah[am], b[an]);
                    if (SPLIT) mma_f16(acc[am][an], al[am], b[an]);
                }
        }
        __syncthreads();
    }

#pragma unroll
    for (int am = 0; am < 2; am++)
#pragma unroll
        for (int an = 0; an < 8; an++) {
            int r = m0 + wm*32 + am*16 + g;
            int cc = n0 + wn*64 + an*8 + tg*2;
            *(float2*)(Cm + (size_t)r*N + cc)     = make_float2(acc[am][an][0], acc[am][an][1]);
            *(float2*)(Cm + (size_t)(r+8)*N + cc) = make_float2(acc[am][an][2], acc[am][an][3]);
        }
}

// Fused QKV: grid.x = 12 -> 8 Q n-tiles, 2 K, 2 V. One full-occupancy launch.
// minBlocksPerMultiprocessor=2 caps regs at 128 -> 2 CTAs/SM (fixes the
// 130-reg / 12.4%-occupancy accident ncu exposed on the proj kernel).
__global__ __launch_bounds__(256, 2) void gemm_qkv(
    const float* __restrict__ x,
    const float* __restrict__ Wq, const float* __restrict__ Wk,
    const float* __restrict__ Wv,
    float* __restrict__ qt, float* __restrict__ kt, float* __restrict__ vt)
{
    __shared__ uint32_t Ah[128*GLD];
    __shared__ uint32_t Bs[128*GLD];
    const int bx = blockIdx.x;
    const int m0 = blockIdx.y * 128;
    const float* Bw; float* Cm; int N, n0;
    if (bx < 8)       { Bw = Wq; Cm = qt; N = CCd;       n0 = bx*128; }
    else if (bx < 10) { Bw = Wk; Cm = kt; N = NKVh*HDd;  n0 = (bx-8)*128; }
    else              { Bw = Wv; Cm = vt; N = NKVh*HDd;  n0 = (bx-10)*128; }
    gemm_body<false>(x, Bw, Cm, N, CCd, m0, n0, Ah, nullptr, Bs);
}

// Wproj with hi/lo split (near-fp32 output precision), 2 CTAs/SM
__global__ __launch_bounds__(256, 2) void gemm_proj(
    const float* __restrict__ A, const float* __restrict__ Bw,
    float* __restrict__ Cm)
{
    __shared__ uint32_t Ah[128*GLD];
    __shared__ uint32_t Al[128*GLD];
    __shared__ uint32_t Bs[128*GLD];
    gemm_body<true>(A, Bw, Cm, CCd, CCd, blockIdx.y*128, blockIdx.x*128, Ah, Al, Bs);
}

// ---------------------------------------------------------------------------
// Postprocess -> fp16 Q/K/V (unchanged)
// ---------------------------------------------------------------------------
__device__ __forceinline__ float warpsum32(float v) {
#pragma unroll
    for (int o = 16; o > 0; o >>= 1) v += __shfl_xor_sync(0xffffffffu, v, o);
    return v;
}

__global__ void postproc(const float* __restrict__ x,   const float* __restrict__ ve,
                         const float* __restrict__ cosT,const float* __restrict__ sinT,
                         const float* __restrict__ Wg,  const float* __restrict__ memk,
                         const float* __restrict__ memv,const float* __restrict__ vscale)
{
    const int gg   = blockIdx.x * blockDim.x + threadIdx.x;
    const int w    = gg >> 5;
    const int lane = gg & 31;
    const int NQ = BB*TT*NHh;
    const int NK = BB*TT*NKVh;
    const int NV = NK;

    if (w < NQ) {
        int h = w % NHh; int t = (w / NHh) % TT; int b = w / (NHh * TT);
        const float* src = g_qt + (size_t)(b*TT + t) * CCd + h * HDd;
        float x1 = src[lane], x2 = src[lane + 32];
        float c = cosT[t*32 + lane], s = sinT[t*32 + lane];
        float o1 = x1*c - x2*s, o2 = x1*s + x2*c;
        float ss = warpsum32(o1*o1 + o2*o2);
        float r = rsqrtf(ss * (1.0f/HDd) + 1e-6f) * 1.2f;
        __half* dst = g_qh + (size_t)((b*NHh + h)*TT + t) * HDd;
        dst[lane] = __float2half(o1*r); dst[lane + 32] = __float2half(o2*r);
    } else if (w < NQ + NK) {
        int w2 = w - NQ;
        int n = w2 % NKVh; int t = (w2 / NKVh) % TT; int b = w2 / (NKVh * TT);
        const float* src = g_kt + (size_t)(b*TT + t) * (NKVh*HDd) + n * HDd;
        float x1 = src[lane], x2 = src[lane + 32];
        float c = cosT[t*32 + lane], s = sinT[t*32 + lane];
        float o1 = x1*c - x2*s, o2 = x1*s + x2*c;
        float ss = warpsum32(o1*o1 + o2*o2);
        float r = rsqrtf(ss * (1.0f/HDd) + 1e-6f) * 1.2f;
        __half* dst = g_kh + (size_t)((b*NKVh + n)*SSs + (MMem + t)) * HDd;
        dst[lane] = __float2half(o1*r); dst[lane + 32] = __float2half(o2*r);
    } else if (w < NQ + NK + NV) {
        int w3 = w - NQ - NK;
        int n = w3 % NKVh; int t = (w3 / NKVh) % TT; int b = w3 / (NKVh * TT);
        float gp = x[(size_t)(b*TT + t)*CCd + lane] * Wg[n*32 + lane];
        float dot = warpsum32(gp);
        float gate = 3.0f / (1.0f + __expf(-dot));
        const float* src = g_vt + (size_t)(b*TT + t) * (NKVh*HDd) + n * HDd;
        const float* vep = ve  + (size_t)(b*TT + t) * (NKVh*HDd) + n * HDd;
        float o1 = src[lane]      + gate * vep[lane];
        float o2 = src[lane + 32] + gate * vep[lane + 32];
        __half* dst = g_vh + (size_t)((b*NKVh + n)*SSs + (MMem + t)) * HDd;
        dst[lane] = __float2half(o1); dst[lane + 32] = __float2half(o2);
    } else {
        int w4 = w - NQ - NK - NV;
        int n = w4 % NKVh; int j = (w4 / NKVh) % MMem; int b = w4 / (NKVh * MMem);
        const float* mkp = memk + (size_t)(j*NKVh + n) * HDd;
        float x1 = mkp[lane], x2 = mkp[lane + 32];
        float ss = warpsum32(x1*x1 + x2*x2);
        float r = rsqrtf(ss * (1.0f/HDd) + 1e-6f) * 1.2f;
        __half* kd = g_kh + (size_t)((b*NKVh + n)*SSs + j) * HDd;
        kd[lane] = __float2half(x1*r); kd[lane + 32] = __float2half(x2*r);
        const float* mvp = memv + (size_t)(j*NKVh + n) * HDd;
        float vs = vscale[0];
        __half* vd = g_vh + (size_t)((b*NKVh + n)*SSs + j) * HDd;
        vd[lane] = __float2half(mvp[lane] * vs); vd[lane + 32] = __float2half(mvp[lane + 32] * vs);
    }
}

// ---------------------------------------------------------------------------
// fp16 flash attention, 128-key tiles, synchronous K/V loads,
// P kept in registers (C-frag of S == A-frag for PV, m16n8k16).
// Dyn smem: K 18432 + V 18432 = 36864 B.  (unchanged from R12)
// ---------------------------------------------------------------------------
#define KLD 36   // u32 per K/V row = 144 B
#define ATTN_SMEM (2*128*KLD*4)   // 36864 B

__global__ __launch_bounds__(256) void attn_f16()
{
    extern __shared__ uint32_t sm[];
    uint32_t* Ks = sm;
    uint32_t* Vs = sm + 128*KLD;

    const int tid = threadIdx.x;
    const int lane = tid & 31, wid = tid >> 5;
    const int g = lane >> 2, tg = lane & 3;
    const int qi = (int)(gridDim.x - 1 - blockIdx.x);   // long blocks first
    const int h = blockIdx.y, b = blockIdx.z;
    const int t0 = qi * 128;
    const int kvh = h >> 2;

    const __half* qptr = g_qh + (size_t)(b*NHh  + h  ) * TT  * HDd;
    const __half* kptr = g_kh + (size_t)(b*NKVh + kvh) * SSs * HDd;
    const __half* vptr = g_vh + (size_t)(b*NKVh + kvh) * SSs * HDd;

    const uint32_t ks_b = smem_u32(Ks);
    const uint32_t vs_b = smem_u32(Vs);

    // ldmatrix lane->address components (identical to R7-R12)
    const int koK = (lane & 7) + ((lane & 16) >> 1);
    const int doK = lane & 8;
    const int koV = lane & 15;
    const int doV = (lane & 16) >> 1;

    // Q fragments (fp16 gmem -> direct u32 loads)
    const int rq1 = t0 + wid*16 + g;
    uint32_t qa[4][4];
#pragma unroll
    for (int s8 = 0; s8 < 4; s8++) {
        int d0 = s8*16 + 2*tg;
        qa[s8][0] = *(const uint32_t*)(qptr + (size_t)rq1*HDd + d0);
        qa[s8][1] = *(const uint32_t*)(qptr + (size_t)(rq1+8)*HDd + d0);
        qa[s8][2] = *(const uint32_t*)(qptr + (size_t)rq1*HDd + d0 + 8);
        qa[s8][3] = *(const uint32_t*)(qptr + (size_t)(rq1+8)*HDd + d0 + 8);
    }

    float o[8][4] = {};
    float m1 = -INFINITY, m2 = -INFINITY, l1 = 0.0f, l2 = 0.0f;

    const int nkt = qi + 2;
    for (int kt = 0; kt < nkt; kt++) {
        __syncthreads();
        // load K/V tiles: 128 rows x 64 halfs each (clamped; overruns masked)
#pragma unroll
        for (int q = 0; q < 4; q++) {
            int idx = q * 256 + tid;
            int row = idx >> 3, c8 = idx & 7;
            int kr = kt*128 + row; if (kr > SSs - 1) kr = SSs - 1;
            *(uint4*)&Ks[row*KLD + c8*4] = *(const uint4*)(kptr + (size_t)kr*HDd + c8*8);
            *(uint4*)&Vs[row*KLD + c8*4] = *(const uint4*)(vptr + (size_t)kr*HDd + c8*8);
        }
        __syncthreads();

        // S = Q K^T : warp computes 16 rows x 128 keys
        float s[16][4] = {};
#pragma unroll
        for (int s8 = 0; s8 < 4; s8++) {
#pragma unroll
            for (int anp = 0; anp < 8; anp++) {
                uint32_t r0, r1, r2, r3;
                uint32_t addr = ks_b + (((anp*16 + koK)*72) + s8*16 + doK) * 2;
                LDSM_X4(r0, r1, r2, r3, addr);
                uint32_t b0[2] = {r0, r1}, b1[2] = {r2, r3};
                mma_f16(s[2*anp],   qa[s8], b0);
                mma_f16(s[2*anp+1], qa[s8], b1);
            }
        }

        // scale + causal mask (key seq pos = kt*128 + col - M)
        const bool dg = (kt >= qi);
#pragma unroll
        for (int an = 0; an < 16; an++) {
            int j0 = kt*128 + an*8 + tg*2 - MMem;
            s[an][0] *= 0.125f; s[an][1] *= 0.125f;
            s[an][2] *= 0.125f; s[an][3] *= 0.125f;
            if (dg) {
                if (j0     > rq1)   s[an][0] = -INFINITY;
                if (j0 + 1 > rq1)   s[an][1] = -INFINITY;
                if (j0     > rq1+8) s[an][2] = -INFINITY;
                if (j0 + 1 > rq1+8) s[an][3] = -INFINITY;
            }
        }

        // online softmax
        float tm1 = -INFINITY, tm2 = -INFINITY;
#pragma unroll
        for (int an = 0; an < 16; an++) {
            tm1 = fmaxf(tm1, fmaxf(s[an][0], s[an][1]));
            tm2 = fmaxf(tm2, fmaxf(s[an][2], s[an][3]));
        }
        tm1 = fmaxf(tm1, __shfl_xor_sync(0xffffffffu, tm1, 1));
        tm1 = fmaxf(tm1, __shfl_xor_sync(0xffffffffu, tm1, 2));
        tm2 = fmaxf(tm2, __shfl_xor_sync(0xffffffffu, tm2, 1));
        tm2 = fmaxf(tm2, __shfl_xor_sync(0xffffffffu, tm2, 2));

        float mn1 = fmaxf(m1, tm1), mn2 = fmaxf(m2, tm2);
        float sc1 = __expf(m1 - mn1), sc2 = __expf(m2 - mn2);
        m1 = mn1; m2 = mn2;
        l1 *= sc1; l2 *= sc2;
#pragma unroll
        for (int dn = 0; dn < 8; dn++) {
            o[dn][0] *= sc1; o[dn][1] *= sc1;
            o[dn][2] *= sc2; o[dn][3] *= sc2;
        }
        float rs1 = 0.0f, rs2 = 0.0f;
#pragma unroll
        for (int an = 0; an < 16; an++) {
            s[an][0] = __expf(s[an][0] - mn1); s[an][1] = __expf(s[an][1] - mn1);
            s[an][2] = __expf(s[an][2] - mn2); s[an][3] = __expf(s[an][3] - mn2);
            rs1 += s[an][0] + s[an][1];
            rs2 += s[an][2] + s[an][3];
        }
        rs1 += __shfl_xor_sync(0xffffffffu, rs1, 1);
        rs1 += __shfl_xor_sync(0xffffffffu, rs1, 2);
        rs2 += __shfl_xor_sync(0xffffffffu, rs2, 1);
        rs2 += __shfl_xor_sync(0xffffffffu, rs2, 2);
        l1 += rs1; l2 += rs2;

        // O += P V  — P taken straight from the S C-fragments (no smem!)
#pragma unroll
        for (int k8 = 0; k8 < 8; k8++) {
            uint32_t a[4];
            a[0] = packh(s[2*k8][0],   s[2*k8][1]);
            a[1] = packh(s[2*k8][2],   s[2*k8][3]);
            a[2] = packh(s[2*k8+1][0], s[2*k8+1][1]);
            a[3] = packh(s[2*k8+1][2], s[2*k8+1][3]);
            uint32_t vrow = vs_b + (((k8*16 + koV)*72) + doV) * 2;
#pragma unroll
            for (int dnp = 0; dnp < 4; dnp++) {
                uint32_t r0, r1, r2, r3;
                LDSM_X4_T(r0, r1, r2, r3, vrow + dnp*32);
                uint32_t b0[2] = {r0, r1}, b1[2] = {r2, r3};
                mma_f16(o[2*dnp],   a, b0);
                mma_f16(o[2*dnp+1], a, b1);
            }
        }
    }

    // finalize
    const float il1 = 1.0f / l1, il2 = 1.0f / l2;
    float* y1 = g_y + (size_t)(b*TT + rq1 - 0) * (NHh*HDd) + h*HDd;
    float* y2 = g_y + (size_t)(b*TT + rq1 + 8) * (NHh*HDd) + h*HDd;
#pragma unroll
    for (int dn = 0; dn < 8; dn++) {
        int cc = dn*8 + tg*2;
        *(float2*)(y1 + cc) = make_float2(o[dn][0]*il1, o[dn][1]*il1);
        *(float2*)(y2 + cc) = make_float2(o[dn][2]*il2, o[dn][3]*il2);
    }
}

// ---------------------------------------------------------------------------
extern "C" void kernel_launch(void* const* d_in, const int* in_sizes, int n_in,
                              void* d_out, int out_size)
{
    const float* x      = (const float*)d_in[0];
    const float* ve     = (const float*)d_in[1];
    const float* cosT   = (const float*)d_in[2];
    const float* sinT   = (const float*)d_in[3];
    const float* Wq     = (const float*)d_in[4];
    const float* Wk     = (const float*)d_in[5];
    const float* Wv     = (const float*)d_in[6];
    const float* Wproj  = (const float*)d_in[7];
    const float* Wg     = (const float*)d_in[8];
    const float* memk   = (const float*)d_in[9];
    const float* memv   = (const float*)d_in[10];
    const float* vscale = (const float*)d_in[11];
    float* out = (float*)d_out;

    void *p_qt, *p_kt, *p_vt, *p_y;
    cudaGetSymbolAddress(&p_qt, g_qt);
    cudaGetSymbolAddress(&p_kt, g_kt);
    cudaGetSymbolAddress(&p_vt, g_vt);
    cudaGetSymbolAddress(&p_y,  g_y);

    const int Mrows = BB * TT;   // 4096
    cudaFuncSetAttribute(attn_f16, cudaFuncAttributeMaxDynamicSharedMemorySize, ATTN_SMEM);

    // Fused QKV projections: one launch, 12x32 = 384 blocks, 2 CTAs/SM
    gemm_qkv<<<dim3(12, Mrows/128), 256>>>(x, Wq, Wk, Wv,
                                           (float*)p_qt, (float*)p_kt, (float*)p_vt);

    // RoPE + RMS + gate + memory concat -> fp16 Q/K/V
    {
        const int nwarps = BB*TT*NHh + BB*TT*NKVh + BB*TT*NKVh + BB*MMem*NKVh;  // 98816
        postproc<<<(nwarps * 32) / 256, 256>>>(x, ve, cosT, sinT, Wg, memk, memv, vscale);
    }

    // Flash attention (fp16, 128-key tiles, P-in-regs)
    attn_f16<<<dim3(TT/128, NHh, BB), 256, ATTN_SMEM>>>();

    // Output projection (fp16 with A hi/lo split, 2 CTAs/SM)
    gemm_proj<<<dim3(CCd/128, Mrows/128), 256>>>((const float*)p_y, Wproj, out);
}

// round 14
// speedup vs baseline: 1.6924x; 1.0435x over previous
#include <cuda_runtime.h>
#include <cuda_fp16.h>
#include <math.h>
#include <stdint.h>

// Problem constants
#define BB    2
#define TT    2048
#define CCd   1024
#define NHh   16
#define NKVh  4
#define HDd   64
#define MMem  64
#define SSs   (MMem + TT)   // 2112

// Scratch (device globals; allocation-free per harness rules)
__device__ float  g_qt[BB*TT*NHh*HDd];    // QKV gemm outs: [B*T][1024]
__device__ float  g_kt[BB*TT*NKVh*HDd];   // [B*T][256]
__device__ float  g_vt[BB*TT*NKVh*HDd];   // [B*T][256]
__device__ __half g_qh[BB*NHh*TT*HDd];    // [b][h][t][d]   fp16
__device__ __half g_kh[BB*NKVh*SSs*HDd];  // [b][kv][s][d]  fp16
__device__ __half g_vh[BB*NKVh*SSs*HDd];  // [b][kv][s][d]  fp16
__device__ float  g_y [BB*TT*NHh*HDd];    // attn out [B*T][1024]

// ---------------------------------------------------------------------------
// fp16 helpers
// ---------------------------------------------------------------------------
__device__ __forceinline__ uint32_t h2u(__half2 h) { return *(uint32_t*)&h; }
__device__ __forceinline__ uint32_t packh(float a, float b) {
    __half2 t = __floats2half2_rn(a, b);
    return h2u(t);
}

__device__ __forceinline__ void mma_f16(float* c, const uint32_t* a, const uint32_t* b) {
    asm("mma.sync.aligned.m16n8k16.row.col.f32.f16.f16.f32 "
        "{%0,%1,%2,%3},{%4,%5,%6,%7},{%8,%9},{%0,%1,%2,%3};"
        : "+f"(c[0]), "+f"(c[1]), "+f"(c[2]), "+f"(c[3])
        : "r"(a[0]), "r"(a[1]), "r"(a[2]), "r"(a[3]), "r"(b[0]), "r"(b[1]));
}

#define LDSM_X4(r0,r1,r2,r3,addr) \
    asm volatile("ldmatrix.sync.aligned.m8n8.x4.shared.b16 {%0,%1,%2,%3}, [%4];" \
                 : "=r"(r0), "=r"(r1), "=r"(r2), "=r"(r3) : "r"(addr))
#define LDSM_X4_T(r0,r1,r2,r3,addr) \
    asm volatile("ldmatrix.sync.aligned.m8n8.x4.trans.shared.b16 {%0,%1,%2,%3}, [%4];" \
                 : "=r"(r0), "=r"(r1), "=r"(r2), "=r"(r3) : "r"(addr))

__device__ __forceinline__ uint32_t smem_u32(const void* p) {
    uint32_t a;
    asm("{ .reg .u64 t; cvta.to.shared.u64 t, %1; cvt.u32.u64 %0, t; }" : "=r"(a) : "l"(p));
    return a;
}

// ---------------------------------------------------------------------------
// GEMM body (shared by fused-QKV and Wproj kernels).
// C[m][n] = sum_k A[m][k]*Bw[n][k].  Block 128x128, K-tile 32, 8 warps 4x2.
// Fragment loads via ldmatrix.x4 (8 LDSM vs 32 scalar LDS per k16 step).
// SPLIT adds A-side hi/lo correction (near-fp32 A) — used for Wproj only.
// smem pitch 20 u32/row: 8-row LDSM starts at banks {0,20,8,28,16,4,24,12}
// -> conflict-free.
// ---------------------------------------------------------------------------
#define GLD 20
template<bool SPLIT>
__device__ __forceinline__ void gemm_body(
    const float* __restrict__ A, const float* __restrict__ Bw,
    float* __restrict__ Cm, int N, int K, int m0, int n0,
    uint32_t* Ah, uint32_t* Al, uint32_t* Bs)
{
    const int tid = threadIdx.x;
    const int lane = tid & 31, wid = tid >> 5;
    const int wm = wid & 3, wn = wid >> 2;
    const int g = lane >> 2, tg = lane & 3;

    const uint32_t ah_b = smem_u32(Ah);
    const uint32_t al_b = SPLIT ? smem_u32(Al) : 0u;
    const uint32_t bs_b = smem_u32(Bs);

    // ldmatrix lane->address components (half units within a row-pitch of 40)
    const int roA = lane & 15;             // A row offset
    const int doA = (lane & 16) >> 1;      // A k offset (+8 halfs for lanes>=16)
    const int koB = (lane & 7) + ((lane & 16) >> 1);   // B row (n) offset
    const int doB = lane & 8;              // B k offset

    float acc[2][8][4] = {};

    for (int k0 = 0; k0 < K; k0 += 32) {
#pragma unroll
        for (int q = 0; q < 4; q++) {
            int idx = q * 256 + tid;
            int row = idx >> 3, kq = (idx & 7) * 4;
            float4 av = *(const float4*)(A + (size_t)(m0 + row) * K + k0 + kq);
            __half2 h0 = __floats2half2_rn(av.x, av.y);
            __half2 h1 = __floats2half2_rn(av.z, av.w);
            *(uint2*)&Ah[row*GLD + (kq >> 1)] = make_uint2(h2u(h0), h2u(h1));
            if (SPLIT) {
                float2 f0 = __half22float2(h0), f1 = __half22float2(h1);
                *(uint2*)&Al[row*GLD + (kq >> 1)] = make_uint2(
                    packh(av.x - f0.x, av.y - f0.y), packh(av.z - f1.x, av.w - f1.y));
            }
            float4 bv = *(const float4*)(Bw + (size_t)(n0 + row) * K + k0 + kq);
            *(uint2*)&Bs[row*GLD + (kq >> 1)] = make_uint2(
                packh(bv.x, bv.y), packh(bv.z, bv.w));
        }
        __syncthreads();
#pragma unroll
        for (int ks = 0; ks < 2; ks++) {
            uint32_t ah[2][4], al[2][4], b[8][2];
#pragma unroll
            for (int am = 0; am < 2; am++) {
                uint32_t off = (((wm*32 + am*16 + roA) * 40) + ks*16 + doA) * 2;
                LDSM_X4(ah[am][0], ah[am][1], ah[am][2], ah[am][3], ah_b + off);
                if (SPLIT)
                    LDSM_X4(al[am][0], al[am][1], al[am][2], al[am][3], al_b + off);
            }
#pragma unroll
            for (int anp = 0; anp < 4; anp++) {
                uint32_t off = (((wn*64 + anp*16 + koB) * 40) + ks*16 + doB) * 2;
                LDSM_X4(b[2*anp][0], b[2*anp][1], b[2*anp+1][0], b[2*anp+1][1],
                        bs_b + off);
            }
#pragma unroll
            for (int am = 0; am < 2; am++)
#pragma unroll
                for (int an = 0; an < 8; an++) {
                    mma_f16(acc[am][an], ah[am], b[an]);
                    if (SPLIT) mma_f16(acc[am][an], al[am], b[an]);
                }
        }
        __syncthreads();
    }

#pragma unroll
    for (int am = 0; am < 2; am++)
#pragma unroll
        for (int an = 0; an < 8; an++) {
            int r = m0 + wm*32 + am*16 + g;
            int cc = n0 + wn*64 + an*8 + tg*2;
            *(float2*)(Cm + (size_t)r*N + cc)     = make_float2(acc[am][an][0], acc[am][an][1]);
            *(float2*)(Cm + (size_t)(r+8)*N + cc) = make_float2(acc[am][an][2], acc[am][an][3]);
        }
}

// Fused QKV: grid.x = 12 -> 8 Q n-tiles, 2 K, 2 V. One full-occupancy launch.
__global__ __launch_bounds__(256, 2) void gemm_qkv(
    const float* __restrict__ x,
    const float* __restrict__ Wq, const float* __restrict__ Wk,
    const float* __restrict__ Wv,
    float* __restrict__ qt, float* __restrict__ kt, float* __restrict__ vt)
{
    __shared__ uint32_t Ah[128*GLD];
    __shared__ uint32_t Bs[128*GLD];
    const int bx = blockIdx.x;
    const int m0 = blockIdx.y * 128;
    const float* Bw; float* Cm; int N, n0;
    if (bx < 8)       { Bw = Wq; Cm = qt; N = CCd;       n0 = bx*128; }
    else if (bx < 10) { Bw = Wk; Cm = kt; N = NKVh*HDd;  n0 = (bx-8)*128; }
    else              { Bw = Wv; Cm = vt; N = NKVh*HDd;  n0 = (bx-10)*128; }
    gemm_body<false>(x, Bw, Cm, N, CCd, m0, n0, Ah, nullptr, Bs);
}

// Wproj with hi/lo split (near-fp32 output precision), 2 CTAs/SM
__global__ __launch_bounds__(256, 2) void gemm_proj(
    const float* __restrict__ A, const float* __restrict__ Bw,
    float* __restrict__ Cm)
{
    __shared__ uint32_t Ah[128*GLD];
    __shared__ uint32_t Al[128*GLD];
    __shared__ uint32_t Bs[128*GLD];
    gemm_body<true>(A, Bw, Cm, CCd, CCd, blockIdx.y*128, blockIdx.x*128, Ah, Al, Bs);
}

// ---------------------------------------------------------------------------
// Postprocess -> fp16 Q/K/V (unchanged)
// ---------------------------------------------------------------------------
__device__ __forceinline__ float warpsum32(float v) {
#pragma unroll
    for (int o = 16; o > 0; o >>= 1) v += __shfl_xor_sync(0xffffffffu, v, o);
    return v;
}

__global__ void postproc(const float* __restrict__ x,   const float* __restrict__ ve,
                         const float* __restrict__ cosT,const float* __restrict__ sinT,
                         const float* __restrict__ Wg,  const float* __restrict__ memk,
                         const float* __restrict__ memv,const float* __restrict__ vscale)
{
    const int gg   = blockIdx.x * blockDim.x + threadIdx.x;
    const int w    = gg >> 5;
    const int lane = gg & 31;
    const int NQ = BB*TT*NHh;
    const int NK = BB*TT*NKVh;
    const int NV = NK;

    if (w < NQ) {
        int h = w % NHh; int t = (w / NHh) % TT; int b = w / (NHh * TT);
        const float* src = g_qt + (size_t)(b*TT + t) * CCd + h * HDd;
        float x1 = src[lane], x2 = src[lane + 32];
        float c = cosT[t*32 + lane], s = sinT[t*32 + lane];
        float o1 = x1*c - x2*s, o2 = x1*s + x2*c;
        float ss = warpsum32(o1*o1 + o2*o2);
        float r = rsqrtf(ss * (1.0f/HDd) + 1e-6f) * 1.2f;
        __half* dst = g_qh + (size_t)((b*NHh + h)*TT + t) * HDd;
        dst[lane] = __float2half(o1*r); dst[lane + 32] = __float2half(o2*r);
    } else if (w < NQ + NK) {
        int w2 = w - NQ;
        int n = w2 % NKVh; int t = (w2 / NKVh) % TT; int b = w2 / (NKVh * TT);
        const float* src = g_kt + (size_t)(b*TT + t) * (NKVh*HDd) + n * HDd;
        float x1 = src[lane], x2 = src[lane + 32];
        float c = cosT[t*32 + lane], s = sinT[t*32 + lane];
        float o1 = x1*c - x2*s, o2 = x1*s + x2*c;
        float ss = warpsum32(o1*o1 + o2*o2);
        float r = rsqrtf(ss * (1.0f/HDd) + 1e-6f) * 1.2f;
        __half* dst = g_kh + (size_t)((b*NKVh + n)*SSs + (MMem + t)) * HDd;
        dst[lane] = __float2half(o1*r); dst[lane + 32] = __float2half(o2*r);
    } else if (w < NQ + NK + NV) {
        int w3 = w - NQ - NK;
        int n = w3 % NKVh; int t = (w3 / NKVh) % TT; int b = w3 / (NKVh * TT);
        float gp = x[(size_t)(b*TT + t)*CCd + lane] * Wg[n*32 + lane];
        float dot = warpsum32(gp);
        float gate = 3.0f / (1.0f + __expf(-dot));
        const float* src = g_vt + (size_t)(b*TT + t) * (NKVh*HDd) + n * HDd;
        const float* vep = ve  + (size_t)(b*TT + t) * (NKVh*HDd) + n * HDd;
        float o1 = src[lane]      + gate * vep[lane];
        float o2 = src[lane + 32] + gate * vep[lane + 32];
        __half* dst = g_vh + (size_t)((b*NKVh + n)*SSs + (MMem + t)) * HDd;
        dst[lane] = __float2half(o1); dst[lane + 32] = __float2half(o2);
    } else {
        int w4 = w - NQ - NK - NV;
        int n = w4 % NKVh; int j = (w4 / NKVh) % MMem; int b = w4 / (NKVh * MMem);
        const float* mkp = memk + (size_t)(j*NKVh + n) * HDd;
        float x1 = mkp[lane], x2 = mkp[lane + 32];
        float ss = warpsum32(x1*x1 + x2*x2);
        float r = rsqrtf(ss * (1.0f/HDd) + 1e-6f) * 1.2f;
        __half* kd = g_kh + (size_t)((b*NKVh + n)*SSs + j) * HDd;
        kd[lane] = __float2half(x1*r); kd[lane + 32] = __float2half(x2*r);
        const float* mvp = memv + (size_t)(j*NKVh + n) * HDd;
        float vs = vscale[0];
        __half* vd = g_vh + (size_t)((b*NKVh + n)*SSs + j) * HDd;
        vd[lane] = __float2half(mvp[lane] * vs); vd[lane + 32] = __float2half(mvp[lane + 32] * vs);
    }
}

// ---------------------------------------------------------------------------
// fp16 flash attention, 128-key tiles, synchronous K/V loads,
// P kept in registers (C-frag of S == A-frag for PV, m16n8k16).
// Dyn smem: K 18432 + V 18432 = 36864 B.  (unchanged from R13)
// ---------------------------------------------------------------------------
#define KLD 36   // u32 per K/V row = 144 B
#define ATTN_SMEM (2*128*KLD*4)   // 36864 B

__global__ __launch_bounds__(256) void attn_f16()
{
    extern __shared__ uint32_t sm[];
    uint32_t* Ks = sm;
    uint32_t* Vs = sm + 128*KLD;

    const int tid = threadIdx.x;
    const int lane = tid & 31, wid = tid >> 5;
    const int g = lane >> 2, tg = lane & 3;
    const int qi = (int)(gridDim.x - 1 - blockIdx.x);   // long blocks first
    const int h = blockIdx.y, b = blockIdx.z;
    const int t0 = qi * 128;
    const int kvh = h >> 2;

    const __half* qptr = g_qh + (size_t)(b*NHh  + h  ) * TT  * HDd;
    const __half* kptr = g_kh + (size_t)(b*NKVh + kvh) * SSs * HDd;
    const __half* vptr = g_vh + (size_t)(b*NKVh + kvh) * SSs * HDd;

    const uint32_t ks_b = smem_u32(Ks);
    const uint32_t vs_b = smem_u32(Vs);

    // ldmatrix lane->address components (identical to R7-R13)
    const int koK = (lane & 7) + ((lane & 16) >> 1);
    const int doK = lane & 8;
    const int koV = lane & 15;
    const int doV = (lane & 16) >> 1;

    // Q fragments (fp16 gmem -> direct u32 loads)
    const int rq1 = t0 + wid*16 + g;
    uint32_t qa[4][4];
#pragma unroll
    for (int s8 = 0; s8 < 4; s8++) {
        int d0 = s8*16 + 2*tg;
        qa[s8][0] = *(const uint32_t*)(qptr + (size_t)rq1*HDd + d0);
        qa[s8][1] = *(const uint32_t*)(qptr + (size_t)(rq1+8)*HDd + d0);
        qa[s8][2] = *(const uint32_t*)(qptr + (size_t)rq1*HDd + d0 + 8);
        qa[s8][3] = *(const uint32_t*)(qptr + (size_t)(rq1+8)*HDd + d0 + 8);
    }

    float o[8][4] = {};
    float m1 = -INFINITY, m2 = -INFINITY, l1 = 0.0f, l2 = 0.0f;

    const int nkt = qi + 2;
    for (int kt = 0; kt < nkt; kt++) {
        __syncthreads();
        // load K/V tiles: 128 rows x 64 halfs each (clamped; overruns masked)
#pragma unroll
        for (int q = 0; q < 4; q++) {
            int idx = q * 256 + tid;
            int row = idx >> 3, c8 = idx & 7;
            int kr = kt*128 + row; if (kr > SSs - 1) kr = SSs - 1;
            *(uint4*)&Ks[row*KLD + c8*4] = *(const uint4*)(kptr + (size_t)kr*HDd + c8*8);
            *(uint4*)&Vs[row*KLD + c8*4] = *(const uint4*)(vptr + (size_t)kr*HDd + c8*8);
        }
        __syncthreads();

        // S = Q K^T : warp computes 16 rows x 128 keys
        float s[16][4] = {};
#pragma unroll
        for (int s8 = 0; s8 < 4; s8++) {
#pragma unroll
            for (int anp = 0; anp < 8; anp++) {
                uint32_t r0, r1, r2, r3;
                uint32_t addr = ks_b + (((anp*16 + koK)*72) + s8*16 + doK) * 2;
                LDSM_X4(r0, r1, r2, r3, addr);
                uint32_t b0[2] = {r0, r1}, b1[2] = {r2, r3};
                mma_f16(s[2*anp],   qa[s8], b0);
                mma_f16(s[2*anp+1], qa[s8], b1);
            }
        }

        // scale + causal mask (key seq pos = kt*128 + col - M)
        const bool dg = (kt >= qi);
#pragma unroll
        for (int an = 0; an < 16; an++) {
            int j0 = kt*128 + an*8 + tg*2 - MMem;
            s[an][0] *= 0.125f; s[an][1] *= 0.125f;
            s[an][2] *= 0.125f; s[an][3] *= 0.125f;
            if (dg) {
                if (j0     > rq1)   s[an][0] = -INFINITY;
                if (j0 + 1 > rq1)   s[an][1] = -INFINITY;
                if (j0     > rq1+8) s[an][2] = -INFINITY;
                if (j0 + 1 > rq1+8) s[an][3] = -INFINITY;
            }
        }

        // online softmax
        float tm1 = -INFINITY, tm2 = -INFINITY;
#pragma unroll
        for (int an = 0; an < 16; an++) {
            tm1 = fmaxf(tm1, fmaxf(s[an][0], s[an][1]));
            tm2 = fmaxf(tm2, fmaxf(s[an][2], s[an][3]));
        }
        tm1 = fmaxf(tm1, __shfl_xor_sync(0xffffffffu, tm1, 1));
        tm1 = fmaxf(tm1, __shfl_xor_sync(0xffffffffu, tm1, 2));
        tm2 = fmaxf(tm2, __shfl_xor_sync(0xffffffffu, tm2, 1));
        tm2 = fmaxf(tm2, __shfl_xor_sync(0xffffffffu, tm2, 2));

        float mn1 = fmaxf(m1, tm1), mn2 = fmaxf(m2, tm2);
        float sc1 = __expf(m1 - mn1), sc2 = __expf(m2 - mn2);
        m1 = mn1; m2 = mn2;
        l1 *= sc1; l2 *= sc2;
#pragma unroll
        for (int dn = 0; dn < 8; dn++) {
            o[dn][0] *= sc1; o[dn][1] *= sc1;
            o[dn][2] *= sc2; o[dn][3] *= sc2;
        }
        float rs1 = 0.0f, rs2 = 0.0f;
#pragma unroll
        for (int an = 0; an < 16; an++) {
            s[an][0] = __expf(s[an][0] - mn1); s[an][1] = __expf(s[an][1] - mn1);
            s[an][2] = __expf(s[an][2] - mn2); s[an][3] = __expf(s[an][3] - mn2);
            rs1 += s[an][0] + s[an][1];
            rs2 += s[an][2] + s[an][3];
        }
        rs1 += __shfl_xor_sync(0xffffffffu, rs1, 1);
        rs1 += __shfl_xor_sync(0xffffffffu, rs1, 2);
        rs2 += __shfl_xor_sync(0xffffffffu, rs2, 1);
        rs2 += __shfl_xor_sync(0xffffffffu, rs2, 2);
        l1 += rs1; l2 += rs2;

        // O += P V  — P taken straight from the S C-fragments (no smem!)
#pragma unroll
        for (int k8 = 0; k8 < 8; k8++) {
            uint32_t a[4];
            a[0] = packh(s[2*k8][0],   s[2*k8][1]);
            a[1] = packh(s[2*k8][2],   s[2*k8][3]);
            a[2] = packh(s[2*k8+1][0], s[2*k8+1][1]);
            a[3] = packh(s[2*k8+1][2], s[2*k8+1][3]);
            uint32_t vrow = vs_b + (((k8*16 + koV)*72) + doV) * 2;
#pragma unroll
            for (int dnp = 0; dnp < 4; dnp++) {
                uint32_t r0, r1, r2, r3;
                LDSM_X4_T(r0, r1, r2, r3, vrow + dnp*32);
                uint32_t b0[2] = {r0, r1}, b1[2] = {r2, r3};
                mma_f16(o[2*dnp],   a, b0);
                mma_f16(o[2*dnp+1], a, b1);
            }
        }
    }

    // finalize
    const float il1 = 1.0f / l1, il2 = 1.0f / l2;
    float* y1 = g_y + (size_t)(b*TT + rq1 - 0) * (NHh*HDd) + h*HDd;
    float* y2 = g_y + (size_t)(b*TT + rq1 + 8) * (NHh*HDd) + h*HDd;
#pragma unroll
    for (int dn = 0; dn < 8; dn++) {
        int cc = dn*8 + tg*2;
        *(float2*)(y1 + cc) = make_float2(o[dn][0]*il1, o[dn][1]*il1);
        *(float2*)(y2 + cc) = make_float2(o[dn][2]*il2, o[dn][3]*il2);
    }
}

// ---------------------------------------------------------------------------
extern "C" void kernel_launch(void* const* d_in, const int* in_sizes, int n_in,
                              void* d_out, int out_size)
{
    const float* x      = (const float*)d_in[0];
    const float* ve     = (const float*)d_in[1];
    const float* cosT   = (const float*)d_in[2];
    const float* sinT   = (const float*)d_in[3];
    const float* Wq     = (const float*)d_in[4];
    const float* Wk     = (const float*)d_in[5];
    const float* Wv     = (const float*)d_in[6];
    const float* Wproj  = (const float*)d_in[7];
    const float* Wg     = (const float*)d_in[8];
    const float* memk   = (const float*)d_in[9];
    const float* memv   = (const float*)d_in[10];
    const float* vscale = (const float*)d_in[11];
    float* out = (float*)d_out;

    void *p_qt, *p_kt, *p_vt, *p_y;
    cudaGetSymbolAddress(&p_qt, g_qt);
    cudaGetSymbolAddress(&p_kt, g_kt);
    cudaGetSymbolAddress(&p_vt, g_vt);
    cudaGetSymbolAddress(&p_y,  g_y);

    const int Mrows = BB * TT;   // 4096
    cudaFuncSetAttribute(attn_f16, cudaFuncAttributeMaxDynamicSharedMemorySize, ATTN_SMEM);

    // Fused QKV projections: one launch, 12x32 = 384 blocks, 2 CTAs/SM
    gemm_qkv<<<dim3(12, Mrows/128), 256>>>(x, Wq, Wk, Wv,
                                           (float*)p_qt, (float*)p_kt, (float*)p_vt);

    // RoPE + RMS + gate + memory concat -> fp16 Q/K/V
    {
        const int nwarps = BB*TT*NHh + BB*TT*NKVh + BB*TT*NKVh + BB*MMem*NKVh;  // 98816
        postproc<<<(nwarps * 32) / 256, 256>>>(x, ve, cosT, sinT, Wg, memk, memv, vscale);
    }

    // Flash attention (fp16, 128-key tiles, P-in-regs)
    attn_f16<<<dim3(TT/128, NHh, BB), 256, ATTN_SMEM>>>();

    // Output projection (fp16 with A hi/lo split, ldmatrix fragments)
    gemm_proj<<<dim3(CCd/128, Mrows/128), 256>>>((const float*)p_y, Wproj, out);
}

// round 15
// speedup vs baseline: 1.8746x; 1.1076x over previous
#include <cuda_runtime.h>
#include <cuda_fp16.h>
#include <math.h>
#include <stdint.h>

// Problem constants
#define BB    2
#define TT    2048
#define CCd   1024
#define NHh   16
#define NKVh  4
#define HDd   64
#define MMem  64
#define SSs   (MMem + TT)   // 2112

// Scratch (device globals; allocation-free per harness rules)
__device__ float  g_qt[BB*TT*NHh*HDd];    // QKV gemm outs: [B*T][1024]
__device__ float  g_kt[BB*TT*NKVh*HDd];   // [B*T][256]
__device__ float  g_vt[BB*TT*NKVh*HDd];   // [B*T][256]
__device__ __half g_qh[BB*NHh*TT*HDd];    // [b][h][t][d]   fp16
__device__ __half g_kh[BB*NKVh*SSs*HDd];  // [b][kv][s][d]  fp16
__device__ __half g_vh[BB*NKVh*SSs*HDd];  // [b][kv][s][d]  fp16
// fp16 GEMM operands (pre-converted once per launch)
__device__ __align__(16) __half g_xh [BB*TT*CCd];      // x  fp16
__device__ __align__(16) __half g_wqh[CCd*CCd];        // Wq fp16
__device__ __align__(16) __half g_wkh[NKVh*HDd*CCd];   // Wk fp16
__device__ __align__(16) __half g_wvh[NKVh*HDd*CCd];   // Wv fp16
__device__ __align__(16) __half g_wph[CCd*CCd];        // Wproj fp16
__device__ __align__(16) __half g_yh [BB*TT*CCd];      // attn out hi
__device__ __align__(16) __half g_yl [BB*TT*CCd];      // attn out lo (y - hi)

// ---------------------------------------------------------------------------
// fp16 helpers
// ---------------------------------------------------------------------------
__device__ __forceinline__ uint32_t h2u(__half2 h) { return *(uint32_t*)&h; }
__device__ __forceinline__ uint32_t packh(float a, float b) {
    __half2 t = __floats2half2_rn(a, b);
    return h2u(t);
}

__device__ __forceinline__ void mma_f16(float* c, const uint32_t* a, const uint32_t* b) {
    asm("mma.sync.aligned.m16n8k16.row.col.f32.f16.f16.f32 "
        "{%0,%1,%2,%3},{%4,%5,%6,%7},{%8,%9},{%0,%1,%2,%3};"
        : "+f"(c[0]), "+f"(c[1]), "+f"(c[2]), "+f"(c[3])
        : "r"(a[0]), "r"(a[1]), "r"(a[2]), "r"(a[3]), "r"(b[0]), "r"(b[1]));
}

#define LDSM_X4(r0,r1,r2,r3,addr) \
    asm volatile("ldmatrix.sync.aligned.m8n8.x4.shared.b16 {%0,%1,%2,%3}, [%4];" \
                 : "=r"(r0), "=r"(r1), "=r"(r2), "=r"(r3) : "r"(addr))
#define LDSM_X4_T(r0,r1,r2,r3,addr) \
    asm volatile("ldmatrix.sync.aligned.m8n8.x4.trans.shared.b16 {%0,%1,%2,%3}, [%4];" \
                 : "=r"(r0), "=r"(r1), "=r"(r2), "=r"(r3) : "r"(addr))

__device__ __forceinline__ uint32_t smem_u32(const void* p) {
    uint32_t a;
    asm("{ .reg .u64 t; cvta.to.shared.u64 t, %1; cvt.u32.u64 %0, t; }" : "=r"(a) : "l"(p));
    return a;
}

#define CPA16(dst, src) \
    asm volatile("cp.async.ca.shared.global [%0], [%1], 16;" :: "r"(dst), "l"(src) : "memory")

// ---------------------------------------------------------------------------
// One-shot fp32 -> fp16 conversion of all GEMM operands (x + 4 weights).
// Each thread converts one float4. ~1.7M float4s.
// ---------------------------------------------------------------------------
#define CVT_NX (BB*TT*CCd/4)          // 1048576
#define CVT_NQ (CCd*CCd/4)            // 262144
#define CVT_NK (NKVh*HDd*CCd/4)       // 65536
#define CVT_TOTAL (CVT_NX + CVT_NQ + 2*CVT_NK + CVT_NQ)   // 1703936

__global__ void cvt_all(const float* __restrict__ x,  const float* __restrict__ Wq,
                        const float* __restrict__ Wk, const float* __restrict__ Wv,
                        const float* __restrict__ Wp)
{
    int i = blockIdx.x * blockDim.x + threadIdx.x;
    if (i >= CVT_TOTAL) return;
    const float* s; __half* d; int off;
    if (i < CVT_NX)                       { s = x;  d = g_xh;  off = i; }
    else if (i < CVT_NX + CVT_NQ)         { s = Wq; d = g_wqh; off = i - CVT_NX; }
    else if (i < CVT_NX + CVT_NQ + CVT_NK){ s = Wk; d = g_wkh; off = i - CVT_NX - CVT_NQ; }
    else if (i < CVT_NX + CVT_NQ + 2*CVT_NK)
                                          { s = Wv; d = g_wvh; off = i - CVT_NX - CVT_NQ - CVT_NK; }
    else                                  { s = Wp; d = g_wph; off = i - CVT_NX - CVT_NQ - 2*CVT_NK; }
    float4 v = ((const float4*)s)[off];
    ((uint2*)d)[off] = make_uint2(packh(v.x, v.y), packh(v.z, v.w));
}

// ---------------------------------------------------------------------------
// fp16 GEMM, all operands fp16 in gmem, cp.async double-buffered K-chunks.
// C[m][n] = sum_k A[m][k]*Bw[n][k].  Block 128x128, K-chunk 32, 8 warps 4x2.
// SPLIT adds A-lo correction (A = Ah + Al, near-fp32) — Wproj only.
// smem per matrix tile: 128 rows x 20 u32 (16 data + 4 pad) = 10240 B.
// ---------------------------------------------------------------------------
#define GLD 20
#define TILE_U32 (128*GLD)   // 2560 u32 = 10240 B

template<bool SPLIT>
__device__ __forceinline__ void gemm_body(
    const __half* __restrict__ Ahg, const __half* __restrict__ Alg,
    const __half* __restrict__ Bg,  float* __restrict__ Cm,
    int N, int K, int m0, int n0, uint32_t* sm)
{
    const int tid = threadIdx.x;
    const int lane = tid & 31, wid = tid >> 5;
    const int wm = wid & 3, wn = wid >> 2;
    const int g = lane >> 2, tg = lane & 3;
    const int NMAT = SPLIT ? 3 : 2;
    const uint32_t STAGE_B = NMAT * TILE_U32 * 4;
    const uint32_t sm_b = smem_u32(sm);

    // ldmatrix lane->address components (half units; row pitch = 40 halfs)
    const int roA = lane & 15;
    const int doA = (lane & 16) >> 1;
    const int koB = (lane & 7) + ((lane & 16) >> 1);
    const int doB = lane & 8;

    // fill mapping: 2 chunks of 16B per matrix per thread
    const int ch0 = tid * 2;

    float acc[2][8][4] = {};
    const int nch = K >> 5;

    // prologue: chunk 0 -> stage 0
    {
#pragma unroll
        for (int j = 0; j < 2; j++) {
            int ch = ch0 + j, row = ch >> 2, c16 = ch & 3;
            uint32_t d = sm_b + row*80 + c16*16;
            const size_t so = (size_t)(m0 + row) * K + c16*8;
            CPA16(d, Ahg + so);
            if (SPLIT) CPA16(d + TILE_U32*4, Alg + so);
            CPA16(d + (NMAT-1)*TILE_U32*4, Bg + (size_t)(n0 + row) * K + c16*8);
        }
        asm volatile("cp.async.commit_group;" ::: "memory");
    }

    for (int c = 0; c < nch; c++) {
        if (c + 1 < nch) {
            uint32_t sb = sm_b + ((c+1) & 1) * STAGE_B;
            int k0 = (c+1) * 32;
#pragma unroll
            for (int j = 0; j < 2; j++) {
                int ch = ch0 + j, row = ch >> 2, c16 = ch & 3;
                uint32_t d = sb + row*80 + c16*16;
                const size_t so = (size_t)(m0 + row) * K + k0 + c16*8;
                CPA16(d, Ahg + so);
                if (SPLIT) CPA16(d + TILE_U32*4, Alg + so);
                CPA16(d + (NMAT-1)*TILE_U32*4, Bg + (size_t)(n0 + row) * K + k0 + c16*8);
            }
            asm volatile("cp.async.commit_group;" ::: "memory");
            asm volatile("cp.async.wait_group 1;" ::: "memory");
        } else {
            asm volatile("cp.async.wait_group 0;" ::: "memory");
        }
        __syncthreads();

        const uint32_t ah_b = sm_b + (c & 1) * STAGE_B;
        const uint32_t al_b = ah_b + TILE_U32*4;
        const uint32_t bs_b = ah_b + (NMAT-1)*TILE_U32*4;

#pragma unroll
        for (int ks = 0; ks < 2; ks++) {
            uint32_t ah[2][4], al[2][4], b[8][2];
#pragma unroll
            for (int am = 0; am < 2; am++) {
                uint32_t off = (((wm*32 + am*16 + roA) * 40) + ks*16 + doA) * 2;
                LDSM_X4(ah[am][0], ah[am][1], ah[am][2], ah[am][3], ah_b + off);
                if (SPLIT)
                    LDSM_X4(al[am][0], al[am][1], al[am][2], al[am][3], al_b + off);
            }
#pragma unroll
            for (int anp = 0; anp < 4; anp++) {
                uint32_t off = (((wn*64 + anp*16 + koB) * 40) + ks*16 + doB) * 2;
                LDSM_X4(b[2*anp][0], b[2*anp][1], b[2*anp+1][0], b[2*anp+1][1],
                        bs_b + off);
            }
#pragma unroll
            for (int am = 0; am < 2; am++)
#pragma unroll
                for (int an = 0; an < 8; an++) {
                    mma_f16(acc[am][an], ah[am], b[an]);
                    if (SPLIT) mma_f16(acc[am][an], al[am], b[an]);
                }
        }
        __syncthreads();
    }

#pragma unroll
    for (int am = 0; am < 2; am++)
#pragma unroll
        for (int an = 0; an < 8; an++) {
            int r = m0 + wm*32 + am*16 + g;
            int cc = n0 + wn*64 + an*8 + tg*2;
            *(float2*)(Cm + (size_t)r*N + cc)     = make_float2(acc[am][an][0], acc[am][an][1]);
            *(float2*)(Cm + (size_t)(r+8)*N + cc) = make_float2(acc[am][an][2], acc[am][an][3]);
        }
}

#define QKV_SMEM (2*2*TILE_U32*4)    // 40960 B
#define PROJ_SMEM (2*3*TILE_U32*4)   // 61440 B

// Fused QKV: grid.x = 12 -> 8 Q n-tiles, 2 K, 2 V.
__global__ __launch_bounds__(256, 2) void gemm_qkv(
    float* __restrict__ qt, float* __restrict__ kt, float* __restrict__ vt)
{
    extern __shared__ uint32_t smq[];
    const int bx = blockIdx.x;
    const int m0 = blockIdx.y * 128;
    const __half* Bw; float* Cm; int N, n0;
    if (bx < 8)       { Bw = g_wqh; Cm = qt; N = CCd;      n0 = bx*128; }
    else if (bx < 10) { Bw = g_wkh; Cm = kt; N = NKVh*HDd; n0 = (bx-8)*128; }
    else              { Bw = g_wvh; Cm = vt; N = NKVh*HDd; n0 = (bx-10)*128; }
    gemm_body<false>(g_xh, nullptr, Bw, Cm, N, CCd, m0, n0, smq);
}

// Wproj with A hi/lo split (near-fp32 output precision)
__global__ __launch_bounds__(256, 2) void gemm_proj(float* __restrict__ Cm)
{
    extern __shared__ uint32_t smp[];
    gemm_body<true>(g_yh, g_yl, g_wph, Cm, CCd, CCd,
                    blockIdx.y*128, blockIdx.x*128, smp);
}

// ---------------------------------------------------------------------------
// Postprocess -> fp16 Q/K/V (unchanged)
// ---------------------------------------------------------------------------
__device__ __forceinline__ float warpsum32(float v) {
#pragma unroll
    for (int o = 16; o > 0; o >>= 1) v += __shfl_xor_sync(0xffffffffu, v, o);
    return v;
}

__global__ void postproc(const float* __restrict__ x,   const float* __restrict__ ve,
                         const float* __restrict__ cosT,const float* __restrict__ sinT,
                         const float* __restrict__ Wg,  const float* __restrict__ memk,
                         const float* __restrict__ memv,const float* __restrict__ vscale)
{
    const int gg   = blockIdx.x * blockDim.x + threadIdx.x;
    const int w    = gg >> 5;
    const int lane = gg & 31;
    const int NQ = BB*TT*NHh;
    const int NK = BB*TT*NKVh;
    const int NV = NK;

    if (w < NQ) {
        int h = w % NHh; int t = (w / NHh) % TT; int b = w / (NHh * TT);
        const float* src = g_qt + (size_t)(b*TT + t) * CCd + h * HDd;
        float x1 = src[lane], x2 = src[lane + 32];
        float c = cosT[t*32 + lane], s = sinT[t*32 + lane];
        float o1 = x1*c - x2*s, o2 = x1*s + x2*c;
        float ss = warpsum32(o1*o1 + o2*o2);
        float r = rsqrtf(ss * (1.0f/HDd) + 1e-6f) * 1.2f;
        __half* dst = g_qh + (size_t)((b*NHh + h)*TT + t) * HDd;
        dst[lane] = __float2half(o1*r); dst[lane + 32] = __float2half(o2*r);
    } else if (w < NQ + NK) {
        int w2 = w - NQ;
        int n = w2 % NKVh; int t = (w2 / NKVh) % TT; int b = w2 / (NKVh * TT);
        const float* src = g_kt + (size_t)(b*TT + t) * (NKVh*HDd) + n * HDd;
        float x1 = src[lane], x2 = src[lane + 32];
        float c = cosT[t*32 + lane], s = sinT[t*32 + lane];
        float o1 = x1*c - x2*s, o2 = x1*s + x2*c;
        float ss = warpsum32(o1*o1 + o2*o2);
        float r = rsqrtf(ss * (1.0f/HDd) + 1e-6f) * 1.2f;
        __half* dst = g_kh + (size_t)((b*NKVh + n)*SSs + (MMem + t)) * HDd;
        dst[lane] = __float2half(o1*r); dst[lane + 32] = __float2half(o2*r);
    } else if (w < NQ + NK + NV) {
        int w3 = w - NQ - NK;
        int n = w3 % NKVh; int t = (w3 / NKVh) % TT; int b = w3 / (NKVh * TT);
        float gp = x[(size_t)(b*TT + t)*CCd + lane] * Wg[n*32 + lane];
        float dot = warpsum32(gp);
        float gate = 3.0f / (1.0f + __expf(-dot));
        const float* src = g_vt + (size_t)(b*TT + t) * (NKVh*HDd) + n * HDd;
        const float* vep = ve  + (size_t)(b*TT + t) * (NKVh*HDd) + n * HDd;
        float o1 = src[lane]      + gate * vep[lane];
        float o2 = src[lane + 32] + gate * vep[lane + 32];
        __half* dst = g_vh + (size_t)((b*NKVh + n)*SSs + (MMem + t)) * HDd;
        dst[lane] = __float2half(o1); dst[lane + 32] = __float2half(o2);
    } else {
        int w4 = w - NQ - NK - NV;
        int n = w4 % NKVh; int j = (w4 / NKVh) % MMem; int b = w4 / (NKVh * MMem);
        const float* mkp = memk + (size_t)(j*NKVh + n) * HDd;
        float x1 = mkp[lane], x2 = mkp[lane + 32];
        float ss = warpsum32(x1*x1 + x2*x2);
        float r = rsqrtf(ss * (1.0f/HDd) + 1e-6f) * 1.2f;
        __half* kd = g_kh + (size_t)((b*NKVh + n)*SSs + j) * HDd;
        kd[lane] = __float2half(x1*r); kd[lane + 32] = __float2half(x2*r);
        const float* mvp = memv + (size_t)(j*NKVh + n) * HDd;
        float vs = vscale[0];
        __half* vd = g_vh + (size_t)((b*NKVh + n)*SSs + j) * HDd;
        vd[lane] = __float2half(mvp[lane] * vs); vd[lane + 32] = __float2half(mvp[lane + 32] * vs);
    }
}

// ---------------------------------------------------------------------------
// fp16 flash attention (unchanged core); epilogue now writes y as hi/lo fp16.
// Dyn smem: K 18432 + V 18432 = 36864 B.
// ---------------------------------------------------------------------------
#define KLD 36   // u32 per K/V row = 144 B
#define ATTN_SMEM (2*128*KLD*4)   // 36864 B

__global__ __launch_bounds__(256) void attn_f16()
{
    extern __shared__ uint32_t sm[];
    uint32_t* Ks = sm;
    uint32_t* Vs = sm + 128*KLD;

    const int tid = threadIdx.x;
    const int lane = tid & 31, wid = tid >> 5;
    const int g = lane >> 2, tg = lane & 3;
    const int qi = (int)(gridDim.x - 1 - blockIdx.x);   // long blocks first
    const int h = blockIdx.y, b = blockIdx.z;
    const int t0 = qi * 128;
    const int kvh = h >> 2;

    const __half* qptr = g_qh + (size_t)(b*NHh  + h  ) * TT  * HDd;
    const __half* kptr = g_kh + (size_t)(b*NKVh + kvh) * SSs * HDd;
    const __half* vptr = g_vh + (size_t)(b*NKVh + kvh) * SSs * HDd;

    const uint32_t ks_b = smem_u32(Ks);
    const uint32_t vs_b = smem_u32(Vs);

    const int koK = (lane & 7) + ((lane & 16) >> 1);
    const int doK = lane & 8;
    const int koV = lane & 15;
    const int doV = (lane & 16) >> 1;

    const int rq1 = t0 + wid*16 + g;
    uint32_t qa[4][4];
#pragma unroll
    for (int s8 = 0; s8 < 4; s8++) {
        int d0 = s8*16 + 2*tg;
        qa[s8][0] = *(const uint32_t*)(qptr + (size_t)rq1*HDd + d0);
        qa[s8][1] = *(const uint32_t*)(qptr + (size_t)(rq1+8)*HDd + d0);
        qa[s8][2] = *(const uint32_t*)(qptr + (size_t)rq1*HDd + d0 + 8);
        qa[s8][3] = *(const uint32_t*)(qptr + (size_t)(rq1+8)*HDd + d0 + 8);
    }

    float o[8][4] = {};
    float m1 = -INFINITY, m2 = -INFINITY, l1 = 0.0f, l2 = 0.0f;

    const int nkt = qi + 2;
    for (int kt = 0; kt < nkt; kt++) {
        __syncthreads();
#pragma unroll
        for (int q = 0; q < 4; q++) {
            int idx = q * 256 + tid;
            int row = idx >> 3, c8 = idx & 7;
            int kr = kt*128 + row; if (kr > SSs - 1) kr = SSs - 1;
            *(uint4*)&Ks[row*KLD + c8*4] = *(const uint4*)(kptr + (size_t)kr*HDd + c8*8);
            *(uint4*)&Vs[row*KLD + c8*4] = *(const uint4*)(vptr + (size_t)kr*HDd + c8*8);
        }
        __syncthreads();

        float s[16][4] = {};
#pragma unroll
        for (int s8 = 0; s8 < 4; s8++) {
#pragma unroll
            for (int anp = 0; anp < 8; anp++) {
                uint32_t r0, r1, r2, r3;
                uint32_t addr = ks_b + (((anp*16 + koK)*72) + s8*16 + doK) * 2;
                LDSM_X4(r0, r1, r2, r3, addr);
                uint32_t b0[2] = {r0, r1}, b1[2] = {r2, r3};
                mma_f16(s[2*anp],   qa[s8], b0);
                mma_f16(s[2*anp+1], qa[s8], b1);
            }
        }

        const bool dg = (kt >= qi);
#pragma unroll
        for (int an = 0; an < 16; an++) {
            int j0 = kt*128 + an*8 + tg*2 - MMem;
            s[an][0] *= 0.125f; s[an][1] *= 0.125f;
            s[an][2] *= 0.125f; s[an][3] *= 0.125f;
            if (dg) {
                if (j0     > rq1)   s[an][0] = -INFINITY;
                if (j0 + 1 > rq1)   s[an][1] = -INFINITY;
                if (j0     > rq1+8) s[an][2] = -INFINITY;
                if (j0 + 1 > rq1+8) s[an][3] = -INFINITY;
            }
        }

        float tm1 = -INFINITY, tm2 = -INFINITY;
#pragma unroll
        for (int an = 0; an < 16; an++) {
            tm1 = fmaxf(tm1, fmaxf(s[an][0], s[an][1]));
            tm2 = fmaxf(tm2, fmaxf(s[an][2], s[an][3]));
        }
        tm1 = fmaxf(tm1, __shfl_xor_sync(0xffffffffu, tm1, 1));
        tm1 = fmaxf(tm1, __shfl_xor_sync(0xffffffffu, tm1, 2));
        tm2 = fmaxf(tm2, __shfl_xor_sync(0xffffffffu, tm2, 1));
        tm2 = fmaxf(tm2, __shfl_xor_sync(0xffffffffu, tm2, 2));

        float mn1 = fmaxf(m1, tm1), mn2 = fmaxf(m2, tm2);
        float sc1 = __expf(m1 - mn1), sc2 = __expf(m2 - mn2);
        m1 = mn1; m2 = mn2;
        l1 *= sc1; l2 *= sc2;
#pragma unroll
        for (int dn = 0; dn < 8; dn++) {
            o[dn][0] *= sc1; o[dn][1] *= sc1;
            o[dn][2] *= sc2; o[dn][3] *= sc2;
        }
        float rs1 = 0.0f, rs2 = 0.0f;
#pragma unroll
        for (int an = 0; an < 16; an++) {
            s[an][0] = __expf(s[an][0] - mn1); s[an][1] = __expf(s[an][1] - mn1);
            s[an][2] = __expf(s[an][2] - mn2); s[an][3] = __expf(s[an][3] - mn2);
            rs1 += s[an][0] + s[an][1];
            rs2 += s[an][2] + s[an][3];
        }
        rs1 += __shfl_xor_sync(0xffffffffu, rs1, 1);
        rs1 += __shfl_xor_sync(0xffffffffu, rs1, 2);
        rs2 += __shfl_xor_sync(0xffffffffu, rs2, 1);
        rs2 += __shfl_xor_sync(0xffffffffu, rs2, 2);
        l1 += rs1; l2 += rs2;

        // O += P V  — P taken straight from the S C-fragments
#pragma unroll
        for (int k8 = 0; k8 < 8; k8++) {
            uint32_t a[4];
            a[0] = packh(s[2*k8][0],   s[2*k8][1]);
            a[1] = packh(s[2*k8][2],   s[2*k8][3]);
            a[2] = packh(s[2*k8+1][0], s[2*k8+1][1]);
            a[3] = packh(s[2*k8+1][2], s[2*k8+1][3]);
            uint32_t vrow = vs_b + (((k8*16 + koV)*72) + doV) * 2;
#pragma unroll
            for (int dnp = 0; dnp < 4; dnp++) {
                uint32_t r0, r1, r2, r3;
                LDSM_X4_T(r0, r1, r2, r3, vrow + dnp*32);
                uint32_t b0[2] = {r0, r1}, b1[2] = {r2, r3};
                mma_f16(o[2*dnp],   a, b0);
                mma_f16(o[2*dnp+1], a, b1);
            }
        }
    }

    // finalize: write y as hi/lo fp16 pair (hi=rn(y), lo=rn(y-hi)) — same
    // values gemm_proj's split used to compute from fp32 y.
    const float il1 = 1.0f / l1, il2 = 1.0f / l2;
    const size_t i1 = (size_t)(b*TT + rq1)     * CCd + h*HDd;
    const size_t i2 = (size_t)(b*TT + rq1 + 8) * CCd + h*HDd;
#pragma unroll
    for (int dn = 0; dn < 8; dn++) {
        int cc = dn*8 + tg*2;
        float ya = o[dn][0]*il1, yb = o[dn][1]*il1;
        float yc = o[dn][2]*il2, yd = o[dn][3]*il2;
        __half ha = __float2half(ya), hb = __float2half(yb);
        __half hc = __float2half(yc), hd = __float2half(yd);
        *(uint32_t*)(g_yh + i1 + cc) = packh(__half2float(ha), 0.0f) * 0 + h2u(__halves2half2(ha, hb));
        *(uint32_t*)(g_yh + i2 + cc) = h2u(__halves2half2(hc, hd));
        *(uint32_t*)(g_yl + i1 + cc) = packh(ya - __half2float(ha), yb - __half2float(hb));
        *(uint32_t*)(g_yl + i2 + cc) = packh(yc - __half2float(hc), yd - __half2float(hd));
    }
}

// ---------------------------------------------------------------------------
extern "C" void kernel_launch(void* const* d_in, const int* in_sizes, int n_in,
                              void* d_out, int out_size)
{
    const float* x      = (const float*)d_in[0];
    const float* ve     = (const float*)d_in[1];
    const float* cosT   = (const float*)d_in[2];
    const float* sinT   = (const float*)d_in[3];
    const float* Wq     = (const float*)d_in[4];
    const float* Wk     = (const float*)d_in[5];
    const float* Wv     = (const float*)d_in[6];
    const float* Wproj  = (const float*)d_in[7];
    const float* Wg     = (const float*)d_in[8];
    const float* memk   = (const float*)d_in[9];
    const float* memv   = (const float*)d_in[10];
    const float* vscale = (const float*)d_in[11];
    float* out = (float*)d_out;

    void *p_qt, *p_kt, *p_vt;
    cudaGetSymbolAddress(&p_qt, g_qt);
    cudaGetSymbolAddress(&p_kt, g_kt);
    cudaGetSymbolAddress(&p_vt, g_vt);

    const int Mrows = BB * TT;   // 4096
    cudaFuncSetAttribute(attn_f16,  cudaFuncAttributeMaxDynamicSharedMemorySize, ATTN_SMEM);
    cudaFuncSetAttribute(gemm_qkv,  cudaFuncAttributeMaxDynamicSharedMemorySize, QKV_SMEM);
    cudaFuncSetAttribute(gemm_proj, cudaFuncAttributeMaxDynamicSharedMemorySize, PROJ_SMEM);

    // One-shot fp32 -> fp16 conversion of x + all weights
    cvt_all<<<(CVT_TOTAL + 255) / 256, 256>>>(x, Wq, Wk, Wv, Wproj);

    // Fused QKV projections (pure fp16, cp.async pipelined)
    gemm_qkv<<<dim3(12, Mrows/128), 256, QKV_SMEM>>>((float*)p_qt, (float*)p_kt, (float*)p_vt);

    // RoPE + RMS + gate + memory concat -> fp16 Q/K/V
    {
        const int nwarps = BB*TT*NHh + BB*TT*NKVh + BB*TT*NKVh + BB*MMem*NKVh;  // 98816
        postproc<<<(nwarps * 32) / 256, 256>>>(x, ve, cosT, sinT, Wg, memk, memv, vscale);
    }

    // Flash attention (fp16, 128-key tiles, P-in-regs, hi/lo y output)
    attn_f16<<<dim3(TT/128, NHh, BB), 256, ATTN_SMEM>>>();

    // Output projection (fp16 A hi/lo split, cp.async pipelined)
    gemm_proj<<<dim3(CCd/128, Mrows/128), 256, PROJ_SMEM>>>(out);
}

// round 16
// speedup vs baseline: 1.9009x; 1.0141x over previous
#include <cuda_runtime.h>
#include <cuda_fp16.h>
#include <math.h>
#include <stdint.h>

// Problem constants
#define BB    2
#define TT    2048
#define CCd   1024
#define NHh   16
#define NKVh  4
#define HDd   64
#define MMem  64
#define SSs   (MMem + TT)   // 2112

// Scratch (device globals; allocation-free per harness rules)
__device__ float  g_qt[BB*TT*NHh*HDd];    // QKV gemm outs: [B*T][1024]
__device__ float  g_kt[BB*TT*NKVh*HDd];   // [B*T][256]
__device__ float  g_vt[BB*TT*NKVh*HDd];   // [B*T][256]
__device__ __half g_qh[BB*NHh*TT*HDd];    // [b][h][t][d]   fp16
__device__ __half g_kh[BB*NKVh*SSs*HDd];  // [b][kv][s][d]  fp16
__device__ __half g_vh[BB*NKVh*SSs*HDd];  // [b][kv][s][d]  fp16
// fp16 GEMM operands (pre-converted once per launch)
__device__ __align__(16) __half g_xh [BB*TT*CCd];      // x  fp16
__device__ __align__(16) __half g_wqh[CCd*CCd];        // Wq fp16
__device__ __align__(16) __half g_wkh[NKVh*HDd*CCd];   // Wk fp16
__device__ __align__(16) __half g_wvh[NKVh*HDd*CCd];   // Wv fp16
__device__ __align__(16) __half g_wph[CCd*CCd];        // Wproj fp16
__device__ __align__(16) __half g_yh [BB*TT*CCd];      // attn out hi
__device__ __align__(16) __half g_yl [BB*TT*CCd];      // attn out lo (y - hi)

// ---------------------------------------------------------------------------
// fp16 helpers
// ---------------------------------------------------------------------------
__device__ __forceinline__ uint32_t h2u(__half2 h) { return *(uint32_t*)&h; }
__device__ __forceinline__ uint32_t packh(float a, float b) {
    __half2 t = __floats2half2_rn(a, b);
    return h2u(t);
}

__device__ __forceinline__ void mma_f16(float* c, const uint32_t* a, const uint32_t* b) {
    asm("mma.sync.aligned.m16n8k16.row.col.f32.f16.f16.f32 "
        "{%0,%1,%2,%3},{%4,%5,%6,%7},{%8,%9},{%0,%1,%2,%3};"
        : "+f"(c[0]), "+f"(c[1]), "+f"(c[2]), "+f"(c[3])
        : "r"(a[0]), "r"(a[1]), "r"(a[2]), "r"(a[3]), "r"(b[0]), "r"(b[1]));
}

#define LDSM_X4(r0,r1,r2,r3,addr) \
    asm volatile("ldmatrix.sync.aligned.m8n8.x4.shared.b16 {%0,%1,%2,%3}, [%4];" \
                 : "=r"(r0), "=r"(r1), "=r"(r2), "=r"(r3) : "r"(addr))
#define LDSM_X4_T(r0,r1,r2,r3,addr) \
    asm volatile("ldmatrix.sync.aligned.m8n8.x4.trans.shared.b16 {%0,%1,%2,%3}, [%4];" \
                 : "=r"(r0), "=r"(r1), "=r"(r2), "=r"(r3) : "r"(addr))

__device__ __forceinline__ uint32_t smem_u32(const void* p) {
    uint32_t a;
    asm("{ .reg .u64 t; cvta.to.shared.u64 t, %1; cvt.u32.u64 %0, t; }" : "=r"(a) : "l"(p));
    return a;
}

#define CPA16(dst, src) \
    asm volatile("cp.async.ca.shared.global [%0], [%1], 16;" :: "r"(dst), "l"(src) : "memory")

// ---------------------------------------------------------------------------
// One-shot fp32 -> fp16 conversion of all GEMM operands (x + 4 weights).
// ---------------------------------------------------------------------------
#define CVT_NX (BB*TT*CCd/4)          // 1048576
#define CVT_NQ (CCd*CCd/4)            // 262144
#define CVT_NK (NKVh*HDd*CCd/4)       // 65536
#define CVT_TOTAL (CVT_NX + CVT_NQ + 2*CVT_NK + CVT_NQ)   // 1703936

__global__ void cvt_all(const float* __restrict__ x,  const float* __restrict__ Wq,
                        const float* __restrict__ Wk, const float* __restrict__ Wv,
                        const float* __restrict__ Wp)
{
    int i = blockIdx.x * blockDim.x + threadIdx.x;
    if (i >= CVT_TOTAL) return;
    const float* s; __half* d; int off;
    if (i < CVT_NX)                       { s = x;  d = g_xh;  off = i; }
    else if (i < CVT_NX + CVT_NQ)         { s = Wq; d = g_wqh; off = i - CVT_NX; }
    else if (i < CVT_NX + CVT_NQ + CVT_NK){ s = Wk; d = g_wkh; off = i - CVT_NX - CVT_NQ; }
    else if (i < CVT_NX + CVT_NQ + 2*CVT_NK)
                                          { s = Wv; d = g_wvh; off = i - CVT_NX - CVT_NQ - CVT_NK; }
    else                                  { s = Wp; d = g_wph; off = i - CVT_NX - CVT_NQ - 2*CVT_NK; }
    float4 v = ((const float4*)s)[off];
    ((uint2*)d)[off] = make_uint2(packh(v.x, v.y), packh(v.z, v.w));
}

// ---------------------------------------------------------------------------
// fp16 GEMM, all operands fp16 in gmem, cp.async double-buffered K-chunks.
// (unchanged from R15)
// ---------------------------------------------------------------------------
#define GLD 20
#define TILE_U32 (128*GLD)   // 2560 u32 = 10240 B

template<bool SPLIT>
__device__ __forceinline__ void gemm_body(
    const __half* __restrict__ Ahg, const __half* __restrict__ Alg,
    const __half* __restrict__ Bg,  float* __restrict__ Cm,
    int N, int K, int m0, int n0, uint32_t* sm)
{
    const int tid = threadIdx.x;
    const int lane = tid & 31, wid = tid >> 5;
    const int wm = wid & 3, wn = wid >> 2;
    const int g = lane >> 2, tg = lane & 3;
    const int NMAT = SPLIT ? 3 : 2;
    const uint32_t STAGE_B = NMAT * TILE_U32 * 4;
    const uint32_t sm_b = smem_u32(sm);

    const int roA = lane & 15;
    const int doA = (lane & 16) >> 1;
    const int koB = (lane & 7) + ((lane & 16) >> 1);
    const int doB = lane & 8;

    const int ch0 = tid * 2;

    float acc[2][8][4] = {};
    const int nch = K >> 5;

    {
#pragma unroll
        for (int j = 0; j < 2; j++) {
            int ch = ch0 + j, row = ch >> 2, c16 = ch & 3;
            uint32_t d = sm_b + row*80 + c16*16;
            const size_t so = (size_t)(m0 + row) * K + c16*8;
            CPA16(d, Ahg + so);
            if (SPLIT) CPA16(d + TILE_U32*4, Alg + so);
            CPA16(d + (NMAT-1)*TILE_U32*4, Bg + (size_t)(n0 + row) * K + c16*8);
        }
        asm volatile("cp.async.commit_group;" ::: "memory");
    }

    for (int c = 0; c < nch; c++) {
        if (c + 1 < nch) {
            uint32_t sb = sm_b + ((c+1) & 1) * STAGE_B;
            int k0 = (c+1) * 32;
#pragma unroll
            for (int j = 0; j < 2; j++) {
                int ch = ch0 + j, row = ch >> 2, c16 = ch & 3;
                uint32_t d = sb + row*80 + c16*16;
                const size_t so = (size_t)(m0 + row) * K + k0 + c16*8;
                CPA16(d, Ahg + so);
                if (SPLIT) CPA16(d + TILE_U32*4, Alg + so);
                CPA16(d + (NMAT-1)*TILE_U32*4, Bg + (size_t)(n0 + row) * K + k0 + c16*8);
            }
            asm volatile("cp.async.commit_group;" ::: "memory");
            asm volatile("cp.async.wait_group 1;" ::: "memory");
        } else {
            asm volatile("cp.async.wait_group 0;" ::: "memory");
        }
        __syncthreads();

        const uint32_t ah_b = sm_b + (c & 1) * STAGE_B;
        const uint32_t al_b = ah_b + TILE_U32*4;
        const uint32_t bs_b = ah_b + (NMAT-1)*TILE_U32*4;

#pragma unroll
        for (int ks = 0; ks < 2; ks++) {
            uint32_t ah[2][4], al[2][4], b[8][2];
#pragma unroll
            for (int am = 0; am < 2; am++) {
                uint32_t off = (((wm*32 + am*16 + roA) * 40) + ks*16 + doA) * 2;
                LDSM_X4(ah[am][0], ah[am][1], ah[am][2], ah[am][3], ah_b + off);
                if (SPLIT)
                    LDSM_X4(al[am][0], al[am][1], al[am][2], al[am][3], al_b + off);
            }
#pragma unroll
            for (int anp = 0; anp < 4; anp++) {
                uint32_t off = (((wn*64 + anp*16 + koB) * 40) + ks*16 + doB) * 2;
                LDSM_X4(b[2*anp][0], b[2*anp][1], b[2*anp+1][0], b[2*anp+1][1],
                        bs_b + off);
            }
#pragma unroll
            for (int am = 0; am < 2; am++)
#pragma unroll
                for (int an = 0; an < 8; an++) {
                    mma_f16(acc[am][an], ah[am], b[an]);
                    if (SPLIT) mma_f16(acc[am][an], al[am], b[an]);
                }
        }
        __syncthreads();
    }

#pragma unroll
    for (int am = 0; am < 2; am++)
#pragma unroll
        for (int an = 0; an < 8; an++) {
            int r = m0 + wm*32 + am*16 + g;
            int cc = n0 + wn*64 + an*8 + tg*2;
            *(float2*)(Cm + (size_t)r*N + cc)     = make_float2(acc[am][an][0], acc[am][an][1]);
            *(float2*)(Cm + (size_t)(r+8)*N + cc) = make_float2(acc[am][an][2], acc[am][an][3]);
        }
}

#define QKV_SMEM (2*2*TILE_U32*4)    // 40960 B
#define PROJ_SMEM (2*3*TILE_U32*4)   // 61440 B

__global__ __launch_bounds__(256, 2) void gemm_qkv(
    float* __restrict__ qt, float* __restrict__ kt, float* __restrict__ vt)
{
    extern __shared__ uint32_t smq[];
    const int bx = blockIdx.x;
    const int m0 = blockIdx.y * 128;
    const __half* Bw; float* Cm; int N, n0;
    if (bx < 8)       { Bw = g_wqh; Cm = qt; N = CCd;      n0 = bx*128; }
    else if (bx < 10) { Bw = g_wkh; Cm = kt; N = NKVh*HDd; n0 = (bx-8)*128; }
    else              { Bw = g_wvh; Cm = vt; N = NKVh*HDd; n0 = (bx-10)*128; }
    gemm_body<false>(g_xh, nullptr, Bw, Cm, N, CCd, m0, n0, smq);
}

__global__ __launch_bounds__(256, 2) void gemm_proj(float* __restrict__ Cm)
{
    extern __shared__ uint32_t smp[];
    gemm_body<true>(g_yh, g_yl, g_wph, Cm, CCd, CCd,
                    blockIdx.y*128, blockIdx.x*128, smp);
}

// ---------------------------------------------------------------------------
// Postprocess -> fp16 Q/K/V (unchanged)
// ---------------------------------------------------------------------------
__device__ __forceinline__ float warpsum32(float v) {
#pragma unroll
    for (int o = 16; o > 0; o >>= 1) v += __shfl_xor_sync(0xffffffffu, v, o);
    return v;
}

__global__ void postproc(const float* __restrict__ x,   const float* __restrict__ ve,
                         const float* __restrict__ cosT,const float* __restrict__ sinT,
                         const float* __restrict__ Wg,  const float* __restrict__ memk,
                         const float* __restrict__ memv,const float* __restrict__ vscale)
{
    const int gg   = blockIdx.x * blockDim.x + threadIdx.x;
    const int w    = gg >> 5;
    const int lane = gg & 31;
    const int NQ = BB*TT*NHh;
    const int NK = BB*TT*NKVh;
    const int NV = NK;

    if (w < NQ) {
        int h = w % NHh; int t = (w / NHh) % TT; int b = w / (NHh * TT);
        const float* src = g_qt + (size_t)(b*TT + t) * CCd + h * HDd;
        float x1 = src[lane], x2 = src[lane + 32];
        float c = cosT[t*32 + lane], s = sinT[t*32 + lane];
        float o1 = x1*c - x2*s, o2 = x1*s + x2*c;
        float ss = warpsum32(o1*o1 + o2*o2);
        float r = rsqrtf(ss * (1.0f/HDd) + 1e-6f) * 1.2f;
        __half* dst = g_qh + (size_t)((b*NHh + h)*TT + t) * HDd;
        dst[lane] = __float2half(o1*r); dst[lane + 32] = __float2half(o2*r);
    } else if (w < NQ + NK) {
        int w2 = w - NQ;
        int n = w2 % NKVh; int t = (w2 / NKVh) % TT; int b = w2 / (NKVh * TT);
        const float* src = g_kt + (size_t)(b*TT + t) * (NKVh*HDd) + n * HDd;
        float x1 = src[lane], x2 = src[lane + 32];
        float c = cosT[t*32 + lane], s = sinT[t*32 + lane];
        float o1 = x1*c - x2*s, o2 = x1*s + x2*c;
        float ss = warpsum32(o1*o1 + o2*o2);
        float r = rsqrtf(ss * (1.0f/HDd) + 1e-6f) * 1.2f;
        __half* dst = g_kh + (size_t)((b*NKVh + n)*SSs + (MMem + t)) * HDd;
        dst[lane] = __float2half(o1*r); dst[lane + 32] = __float2half(o2*r);
    } else if (w < NQ + NK + NV) {
        int w3 = w - NQ - NK;
        int n = w3 % NKVh; int t = (w3 / NKVh) % TT; int b = w3 / (NKVh * TT);
        float gp = x[(size_t)(b*TT + t)*CCd + lane] * Wg[n*32 + lane];
        float dot = warpsum32(gp);
        float gate = 3.0f / (1.0f + __expf(-dot));
        const float* src = g_vt + (size_t)(b*TT + t) * (NKVh*HDd) + n * HDd;
        const float* vep = ve  + (size_t)(b*TT + t) * (NKVh*HDd) + n * HDd;
        float o1 = src[lane]      + gate * vep[lane];
        float o2 = src[lane + 32] + gate * vep[lane + 32];
        __half* dst = g_vh + (size_t)((b*NKVh + n)*SSs + (MMem + t)) * HDd;
        dst[lane] = __float2half(o1); dst[lane + 32] = __float2half(o2);
    } else {
        int w4 = w - NQ - NK - NV;
        int n = w4 % NKVh; int j = (w4 / NKVh) % MMem; int b = w4 / (NKVh * MMem);
        const float* mkp = memk + (size_t)(j*NKVh + n) * HDd;
        float x1 = mkp[lane], x2 = mkp[lane + 32];
        float ss = warpsum32(x1*x1 + x2*x2);
        float r = rsqrtf(ss * (1.0f/HDd) + 1e-6f) * 1.2f;
        __half* kd = g_kh + (size_t)((b*NKVh + n)*SSs + j) * HDd;
        kd[lane] = __float2half(x1*r); kd[lane + 32] = __float2half(x2*r);
        const float* mvp = memv + (size_t)(j*NKVh + n) * HDd;
        float vs = vscale[0];
        __half* vd = g_vh + (size_t)((b*NKVh + n)*SSs + j) * HDd;
        vd[lane] = __float2half(mvp[lane] * vs); vd[lane + 32] = __float2half(mvp[lane + 32] * vs);
    }
}

// ---------------------------------------------------------------------------
// fp16 flash attention, 128-key tiles, cp.async double-buffered K/V,
// P-in-regs, exp2-domain softmax (log2e folded into the score scale).
// Dyn smem: 2 stages x (K+V) = 2 x 36864 = 73728 B (1 CTA/SM; regs bind).
// ---------------------------------------------------------------------------
#define KLD 36   // u32 per K/V row = 144 B
#define STG_U32 (2*128*KLD)                 // K+V per stage (9216 u32)
#define ATTN_SMEM (2*STG_U32*4)             // 73728 B
#define SCL 0.1803368801111204f             // 0.125 * log2(e)

__global__ __launch_bounds__(256) void attn_f16()
{
    extern __shared__ uint32_t sm[];

    const int tid = threadIdx.x;
    const int lane = tid & 31, wid = tid >> 5;
    const int g = lane >> 2, tg = lane & 3;
    const int qi = (int)(gridDim.x - 1 - blockIdx.x);   // long blocks first
    const int h = blockIdx.y, b = blockIdx.z;
    const int t0 = qi * 128;
    const int kvh = h >> 2;

    const __half* qptr = g_qh + (size_t)(b*NHh  + h  ) * TT  * HDd;
    const __half* kptr = g_kh + (size_t)(b*NKVh + kvh) * SSs * HDd;
    const __half* vptr = g_vh + (size_t)(b*NKVh + kvh) * SSs * HDd;

    const uint32_t sm_b = smem_u32(sm);

    // cp.async fill mapping: 2 threads per row, 4x16B chunks each per matrix
    const int f_row = tid >> 1, f_half = (tid & 1) * 4;

    // ldmatrix lane->address components
    const int koK = (lane & 7) + ((lane & 16) >> 1);
    const int doK = lane & 8;
    const int koV = lane & 15;
    const int doV = (lane & 16) >> 1;

    // Q fragments
    const int rq1 = t0 + wid*16 + g;
    uint32_t qa[4][4];
#pragma unroll
    for (int s8 = 0; s8 < 4; s8++) {
        int d0 = s8*16 + 2*tg;
        qa[s8][0] = *(const uint32_t*)(qptr + (size_t)rq1*HDd + d0);
        qa[s8][1] = *(const uint32_t*)(qptr + (size_t)(rq1+8)*HDd + d0);
        qa[s8][2] = *(const uint32_t*)(qptr + (size_t)rq1*HDd + d0 + 8);
        qa[s8][3] = *(const uint32_t*)(qptr + (size_t)(rq1+8)*HDd + d0 + 8);
    }

    float o[8][4] = {};
    float m1 = -INFINITY, m2 = -INFINITY, l1 = 0.0f, l2 = 0.0f;

    const int nkt = qi + 2;

    // prologue: tile 0 -> stage 0
    {
        int kr = f_row; if (kr > SSs - 1) kr = SSs - 1;
        const __half* kq = kptr + (size_t)kr*HDd + f_half*8;
        const __half* vq = vptr + (size_t)kr*HDd + f_half*8;
        uint32_t kb = sm_b + f_row*144 + f_half*16;
        uint32_t vb = kb + 128*KLD*4;
#pragma unroll
        for (int j = 0; j < 4; j++) { CPA16(kb + j*16, kq + j*8); CPA16(vb + j*16, vq + j*8); }
        asm volatile("cp.async.commit_group;" ::: "memory");
    }

    for (int kt = 0; kt < nkt; kt++) {
        if (kt + 1 < nkt) {
            uint32_t sb = sm_b + ((kt+1) & 1) * STG_U32 * 4;
            int kr = (kt+1)*128 + f_row; if (kr > SSs - 1) kr = SSs - 1;
            const __half* kq = kptr + (size_t)kr*HDd + f_half*8;
            const __half* vq = vptr + (size_t)kr*HDd + f_half*8;
            uint32_t kb = sb + f_row*144 + f_half*16;
            uint32_t vb = kb + 128*KLD*4;
#pragma unroll
            for (int j = 0; j < 4; j++) { CPA16(kb + j*16, kq + j*8); CPA16(vb + j*16, vq + j*8); }
            asm volatile("cp.async.commit_group;" ::: "memory");
            asm volatile("cp.async.wait_group 1;" ::: "memory");
        } else {
            asm volatile("cp.async.wait_group 0;" ::: "memory");
        }
        __syncthreads();

        const uint32_t ks_b = sm_b + (kt & 1) * STG_U32 * 4;
        const uint32_t vs_b = ks_b + 128*KLD*4;

        // S = Q K^T : warp computes 16 rows x 128 keys
        float s[16][4] = {};
#pragma unroll
        for (int s8 = 0; s8 < 4; s8++) {
#pragma unroll
            for (int anp = 0; anp < 8; anp++) {
                uint32_t r0, r1, r2, r3;
                uint32_t addr = ks_b + (((anp*16 + koK)*72) + s8*16 + doK) * 2;
                LDSM_X4(r0, r1, r2, r3, addr);
                uint32_t b0[2] = {r0, r1}, b1[2] = {r2, r3};
                mma_f16(s[2*anp],   qa[s8], b0);
                mma_f16(s[2*anp+1], qa[s8], b1);
            }
        }

        // scale (x log2e, exp2 domain) + causal mask
        const bool dg = (kt >= qi);
#pragma unroll
        for (int an = 0; an < 16; an++) {
            int j0 = kt*128 + an*8 + tg*2 - MMem;
            s[an][0] *= SCL; s[an][1] *= SCL;
            s[an][2] *= SCL; s[an][3] *= SCL;
            if (dg) {
                if (j0     > rq1)   s[an][0] = -INFINITY;
                if (j0 + 1 > rq1)   s[an][1] = -INFINITY;
                if (j0     > rq1+8) s[an][2] = -INFINITY;
                if (j0 + 1 > rq1+8) s[an][3] = -INFINITY;
            }
        }

        // online softmax (exp2 domain)
        float tm1 = -INFINITY, tm2 = -INFINITY;
#pragma unroll
        for (int an = 0; an < 16; an++) {
            tm1 = fmaxf(tm1, fmaxf(s[an][0], s[an][1]));
            tm2 = fmaxf(tm2, fmaxf(s[an][2], s[an][3]));
        }
        tm1 = fmaxf(tm1, __shfl_xor_sync(0xffffffffu, tm1, 1));
        tm1 = fmaxf(tm1, __shfl_xor_sync(0xffffffffu, tm1, 2));
        tm2 = fmaxf(tm2, __shfl_xor_sync(0xffffffffu, tm2, 1));
        tm2 = fmaxf(tm2, __shfl_xor_sync(0xffffffffu, tm2, 2));

        float mn1 = fmaxf(m1, tm1), mn2 = fmaxf(m2, tm2);
        float sc1 = exp2f(m1 - mn1), sc2 = exp2f(m2 - mn2);
        m1 = mn1; m2 = mn2;
        l1 *= sc1; l2 *= sc2;
#pragma unroll
        for (int dn = 0; dn < 8; dn++) {
            o[dn][0] *= sc1; o[dn][1] *= sc1;
            o[dn][2] *= sc2; o[dn][3] *= sc2;
        }
        float rs1 = 0.0f, rs2 = 0.0f;
#pragma unroll
        for (int an = 0; an < 16; an++) {
            s[an][0] = exp2f(s[an][0] - mn1); s[an][1] = exp2f(s[an][1] - mn1);
            s[an][2] = exp2f(s[an][2] - mn2); s[an][3] = exp2f(s[an][3] - mn2);
            rs1 += s[an][0] + s[an][1];
            rs2 += s[an][2] + s[an][3];
        }
        rs1 += __shfl_xor_sync(0xffffffffu, rs1, 1);
        rs1 += __shfl_xor_sync(0xffffffffu, rs1, 2);
        rs2 += __shfl_xor_sync(0xffffffffu, rs2, 1);
        rs2 += __shfl_xor_sync(0xffffffffu, rs2, 2);
        l1 += rs1; l2 += rs2;

        // O += P V  — P taken straight from the S C-fragments
#pragma unroll
        for (int k8 = 0; k8 < 8; k8++) {
            uint32_t a[4];
            a[0] = packh(s[2*k8][0],   s[2*k8][1]);
            a[1] = packh(s[2*k8][2],   s[2*k8][3]);
            a[2] = packh(s[2*k8+1][0], s[2*k8+1][1]);
            a[3] = packh(s[2*k8+1][2], s[2*k8+1][3]);
            uint32_t vrow = vs_b + (((k8*16 + koV)*72) + doV) * 2;
#pragma unroll
            for (int dnp = 0; dnp < 4; dnp++) {
                uint32_t r0, r1, r2, r3;
                LDSM_X4_T(r0, r1, r2, r3, vrow + dnp*32);
                uint32_t b0[2] = {r0, r1}, b1[2] = {r2, r3};
                mma_f16(o[2*dnp],   a, b0);
                mma_f16(o[2*dnp+1], a, b1);
            }
        }
        __syncthreads();   // stage (kt&1) free for tile kt+2's prefetch
    }

    // finalize: write y as hi/lo fp16 pair (hi=rn(y), lo=rn(y-hi))
    const float il1 = 1.0f / l1, il2 = 1.0f / l2;
    const size_t i1 = (size_t)(b*TT + rq1)     * CCd + h*HDd;
    const size_t i2 = (size_t)(b*TT + rq1 + 8) * CCd + h*HDd;
#pragma unroll
    for (int dn = 0; dn < 8; dn++) {
        int cc = dn*8 + tg*2;
        float ya = o[dn][0]*il1, yb = o[dn][1]*il1;
        float yc = o[dn][2]*il2, yd = o[dn][3]*il2;
        __half ha = __float2half(ya), hb = __float2half(yb);
        __half hc = __float2half(yc), hd = __float2half(yd);
        *(uint32_t*)(g_yh + i1 + cc) = h2u(__halves2half2(ha, hb));
        *(uint32_t*)(g_yh + i2 + cc) = h2u(__halves2half2(hc, hd));
        *(uint32_t*)(g_yl + i1 + cc) = packh(ya - __half2float(ha), yb - __half2float(hb));
        *(uint32_t*)(g_yl + i2 + cc) = packh(yc - __half2float(hc), yd - __half2float(hd));
    }
}

// ---------------------------------------------------------------------------
extern "C" void kernel_launch(void* const* d_in, const int* in_sizes, int n_in,
                              void* d_out, int out_size)
{
    const float* x      = (const float*)d_in[0];
    const float* ve     = (const float*)d_in[1];
    const float* cosT   = (const float*)d_in[2];
    const float* sinT   = (const float*)d_in[3];
    const float* Wq     = (const float*)d_in[4];
    const float* Wk     = (const float*)d_in[5];
    const float* Wv     = (const float*)d_in[6];
    const float* Wproj  = (const float*)d_in[7];
    const float* Wg     = (const float*)d_in[8];
    const float* memk   = (const float*)d_in[9];
    const float* memv   = (const float*)d_in[10];
    const float* vscale = (const float*)d_in[11];
    float* out = (float*)d_out;

    void *p_qt, *p_kt, *p_vt;
    cudaGetSymbolAddress(&p_qt, g_qt);
    cudaGetSymbolAddress(&p_kt, g_kt);
    cudaGetSymbolAddress(&p_vt, g_vt);

    const int Mrows = BB * TT;   // 4096
    cudaFuncSetAttribute(attn_f16,  cudaFuncAttributeMaxDynamicSharedMemorySize, ATTN_SMEM);
    cudaFuncSetAttribute(gemm_qkv,  cudaFuncAttributeMaxDynamicSharedMemorySize, QKV_SMEM);
    cudaFuncSetAttribute(gemm_proj, cudaFuncAttributeMaxDynamicSharedMemorySize, PROJ_SMEM);

    // One-shot fp32 -> fp16 conversion of x + all weights
    cvt_all<<<(CVT_TOTAL + 255) / 256, 256>>>(x, Wq, Wk, Wv, Wproj);

    // Fused QKV projections (pure fp16, cp.async pipelined)
    gemm_qkv<<<dim3(12, Mrows/128), 256, QKV_SMEM>>>((float*)p_qt, (float*)p_kt, (float*)p_vt);

    // RoPE + RMS + gate + memory concat -> fp16 Q/K/V
    {
        const int nwarps = BB*TT*NHh + BB*TT*NKVh + BB*TT*NKVh + BB*MMem*NKVh;  // 98816
        postproc<<<(nwarps * 32) / 256, 256>>>(x, ve, cosT, sinT, Wg, memk, memv, vscale);
    }

    // Flash attention (fp16, 128-key tiles, cp.async pipelined, exp2 softmax)
    attn_f16<<<dim3(TT/128, NHh, BB), 256, ATTN_SMEM>>>();

    // Output projection (fp16 A hi/lo split, cp.async pipelined)
    gemm_proj<<<dim3(CCd/128, Mrows/128), 256, PROJ_SMEM>>>(out);
}